// round 10
// baseline (speedup 1.0000x reference)
#include <cuda_runtime.h>
#include <cstdint>

#define NB 2
#define LL 256
#define HH 8
#define DD 64
#define EE 512
#define INVS 0.70710678118654752440f

typedef unsigned long long ull;

__device__ __forceinline__ ull fma2(ull a, ull b, ull c) {
    ull d;
    asm("fma.rn.f32x2 %0, %1, %2, %3;" : "=l"(d) : "l"(a), "l"(b), "l"(c));
    return d;
}
__device__ __forceinline__ ull add2(ull a, ull b) {
    ull d;
    asm("add.rn.f32x2 %0, %1, %2;" : "=l"(d) : "l"(a), "l"(b));
    return d;
}
__device__ __forceinline__ ull pack2(float x, float y) {
    ull d;
    asm("mov.b64 %0, {%1, %2};" : "=l"(d) : "r"(__float_as_uint(x)), "r"(__float_as_uint(y)));
    return d;
}
__device__ __forceinline__ float lohi(ull s) {
    unsigned lo, hi;
    asm("mov.b64 {%0, %1}, %2;" : "=r"(lo), "=r"(hi) : "l"(s));
    return __uint_as_float(lo) + __uint_as_float(hi);
}
__device__ __forceinline__ void unpk(ull s, float& a, float& b) {
    unsigned lo, hi;
    asm("mov.b64 {%0, %1}, %2;" : "=r"(lo), "=r"(hi) : "l"(s));
    a = __uint_as_float(lo);
    b = __uint_as_float(hi);
}

// ---- scratch ----
__device__ float g_qm[NB * LL * EE];   // q @ Wq^T * INVS
__device__ float g_k [NB * LL * EE];   // k @ Wk^T
__device__ float g_pq[NB * LL * EE];   // p @ Wpq^T * INVS
__device__ float g_pk[NB * LL * EE];   // p @ Wpk^T
__device__ float g_a [NB * LL * EE];   // qm @ Wrk  (INVS via qm)
__device__ float g_b [NB * LL * EE];   // (k' @ Wrq) * INVS
__device__ float g_vp[NB * LL * EE];   // v @ Wv^T
__device__ float g_base[NB * HH * LL * LL];
__device__ float g_outh[NB * LL * EE];

// ---- kA1: 5 independent projections y = X@W^T (*scale). grid (8 rt, 8 h, 5 z) ----
__global__ void __launch_bounds__(256)
kA1(const float* __restrict__ query, const float* __restrict__ keys,
    const float* __restrict__ pos,   const float* __restrict__ values,
    const float* __restrict__ Wq,  const float* __restrict__ Wk,
    const float* __restrict__ Wpq, const float* __restrict__ Wpk,
    const float* __restrict__ Wv) {
    __shared__ float Xs[64][68];
    __shared__ float W1s[64][64];   // transposed+swizzled: W1s[m][i'] = W1[i][m]
    const int rt = blockIdx.x, h = blockIdx.y, z = blockIdx.z;
    const int tid = threadIdx.x;
    const int cid = tid & 15, rid = tid >> 4;

    const float* src = (z == 0) ? query : (z == 1) ? keys
                     : (z == 2 || z == 3) ? pos : values;
    const float* W1  = (z == 0) ? Wq : (z == 1) ? Wk
                     : (z == 2) ? Wpq : (z == 3) ? Wpk : Wv;

#pragma unroll
    for (int ii = 0; ii < 4; ii++) {
        int flat = ii * 256 + tid;
        int r = flat >> 4, c4 = flat & 15;
        *(float4*)&Xs[r][c4 * 4] =
            *(const float4*)(src + (size_t)(rt * 64 + r) * 512 + h * 64 + c4 * 4);
    }
#pragma unroll
    for (int ii = 0; ii < 4; ii++) {
        int flat = ii * 256 + tid;
        int i = flat >> 4, m4 = flat & 15;
        float4 wv = *(const float4*)(W1 + (size_t)i * 64 + m4 * 4);
        float w4[4] = {wv.x, wv.y, wv.z, wv.w};
#pragma unroll
        for (int j = 0; j < 4; j++) {
            int m = m4 * 4 + j;
            W1s[m][(((i >> 2) ^ (m & 15)) << 2) + (i & 3)] = w4[j];
        }
    }
    __syncthreads();

    ull acc[4][2];
#pragma unroll
    for (int rj = 0; rj < 4; rj++) { acc[rj][0] = 0; acc[rj][1] = 0; }
#pragma unroll 4
    for (int m = 0; m < 64; m++) {
        ulonglong2 wv = *(const ulonglong2*)&W1s[m][(cid ^ (m & 15)) << 2];
#pragma unroll
        for (int rj = 0; rj < 4; rj++) {
            float xa = Xs[rj * 16 + rid][m];
            ull xa2 = pack2(xa, xa);
            acc[rj][0] = fma2(xa2, wv.x, acc[rj][0]);
            acc[rj][1] = fma2(xa2, wv.y, acc[rj][1]);
        }
    }
    float s1 = (z == 0 || z == 2) ? INVS : 1.0f;
    float* out1 = (z == 0) ? g_qm : (z == 1) ? g_k
                : (z == 2) ? g_pq : (z == 3) ? g_pk : g_vp;
    ull s1v = pack2(s1, s1);
#pragma unroll
    for (int rj = 0; rj < 4; rj++) {
        int row = rj * 16 + rid;
        ulonglong2 o;
        o.x = fma2(acc[rj][0], s1v, 0ull);
        o.y = fma2(acc[rj][1], s1v, 0ull);
        *(ulonglong2*)(out1 + (size_t)(rt * 64 + row) * 512 + h * 64 + cid * 4) = o;
    }
}

// ---- kBA2: merged. blockIdx.x < 16 -> base-GEMM role (kB);
//                    blockIdx.x >= 16 -> second-stage projection role (kA2) ----
__global__ void __launch_bounds__(256)
kBA2(const float* __restrict__ mask, const float* __restrict__ bout,
     float* __restrict__ out,
     const float* __restrict__ Wrk, const float* __restrict__ Wrq) {
    __shared__ float S0[64][68];
    __shared__ float S1[64][68];
    const int tid = threadIdx.x;
    const int jid = tid & 15, rid = tid >> 4;

    if (blockIdx.x >= 16) {
        // ---- kA2 role: z=0: a = qm@Wrk ; z=1: b = (k'@Wrq)*INVS ----
        const int rt = blockIdx.x - 16, h = blockIdx.y, z = blockIdx.z;
        const float* Yin = z ? g_k : g_qm;
        const float* W2  = z ? Wrq : Wrk;
        float (*Ys)[68]  = S0;
        float* W2s = &S1[0][0];   // plain [i][e], stride 64

#pragma unroll
        for (int ii = 0; ii < 4; ii++) {
            int flat = ii * 256 + tid;
            int r = flat >> 4, c4 = flat & 15;
            *(float4*)&Ys[r][c4 * 4] =
                *(const float4*)(Yin + (size_t)(rt * 64 + r) * 512 + h * 64 + c4 * 4);
        }
#pragma unroll
        for (int ii = 0; ii < 4; ii++) {
            int flat = ii * 256 + tid;
            int i = flat >> 4, e4 = flat & 15;
            *(float4*)&W2s[i * 64 + e4 * 4] = *(const float4*)(W2 + (size_t)i * 64 + e4 * 4);
        }
        __syncthreads();

        ull acc[4][2];
#pragma unroll
        for (int rj = 0; rj < 4; rj++) { acc[rj][0] = 0; acc[rj][1] = 0; }
#pragma unroll 4
        for (int i = 0; i < 64; i++) {
            ulonglong2 wv = *(const ulonglong2*)&W2s[i * 64 + jid * 4];
#pragma unroll
            for (int rj = 0; rj < 4; rj++) {
                float ya = Ys[rj * 16 + rid][i];
                ull ya2 = pack2(ya, ya);
                acc[rj][0] = fma2(ya2, wv.x, acc[rj][0]);
                acc[rj][1] = fma2(ya2, wv.y, acc[rj][1]);
            }
        }
        float s2 = z ? INVS : 1.0f;
        float* out2 = z ? g_b : g_a;
        ull s2v = pack2(s2, s2);
#pragma unroll
        for (int rj = 0; rj < 4; rj++) {
            int row = rj * 16 + rid;
            ulonglong2 o;
            o.x = fma2(acc[rj][0], s2v, 0ull);
            o.y = fma2(acc[rj][1], s2v, 0ull);
            *(ulonglong2*)(out2 + (size_t)(rt * 64 + row) * 512 + h * 64 + jid * 4) = o;
        }
        return;
    }

    // ---- kB role: base = (qm|pq).(k'|pk)^T + mask; also write bias rows ----
    const int qt = blockIdx.x >> 2, kt = blockIdx.x & 3;
    const int h = blockIdx.y, n = blockIdx.z;
    float (*As)[68] = S0;
    float (*Bs)[68] = S1;

    // bias init for out (kE accumulates atomically afterwards, same graph)
    {
        int lb = blockIdx.x + 16 * blockIdx.y + 128 * blockIdx.z;   // 0..255
        int row = 2 * lb + (tid >> 7);
        int c4 = (tid & 127) * 4;
        *(float4*)(out + (size_t)row * 512 + c4) = *(const float4*)(bout + c4);
    }

    ull acc[4][2];
#pragma unroll
    for (int qi = 0; qi < 4; qi++) { acc[qi][0] = 0; acc[qi][1] = 0; }

#pragma unroll
    for (int s = 0; s < 2; s++) {
        __syncthreads();
        const float* Aop = s ? g_pq : g_qm;
        const float* Bop = s ? g_pk : g_k;
#pragma unroll
        for (int ii = 0; ii < 8; ii++) {
            int flat = ii * 256 + tid;
            int arr = flat >> 10;                 // 0 = A, 1 = B
            int r = (flat >> 4) & 63;
            int c4 = flat & 15;
            const float* src = arr
                ? Bop + (size_t)(n * 256 + kt * 64 + r) * 512
                : Aop + (size_t)(n * 256 + qt * 64 + r) * 512;
            float4 v = *(const float4*)(src + h * 64 + c4 * 4);
            float* dst = arr ? &Bs[0][0] : &As[0][0];
            float vv[4] = {v.x, v.y, v.z, v.w};
#pragma unroll
            for (int i = 0; i < 4; i++) {
                int c = c4 * 4 + i;
                dst[c * 68 + ((((r >> 2) ^ (c & 15)) << 2) | (r & 3))] = vv[i];
            }
        }
        __syncthreads();
#pragma unroll 4
        for (int c = 0; c < 64; c++) {
            float4 aq = *(const float4*)&As[c][(rid ^ (c & 15)) << 2];
            ulonglong2 bk = *(const ulonglong2*)&Bs[c][(jid ^ (c & 15)) << 2];
            float a4[4] = {aq.x, aq.y, aq.z, aq.w};
#pragma unroll
            for (int qi = 0; qi < 4; qi++) {
                ull a2 = pack2(a4[qi], a4[qi]);
                acc[qi][0] = fma2(a2, bk.x, acc[qi][0]);
                acc[qi][1] = fma2(a2, bk.y, acc[qi][1]);
            }
        }
    }
    float4 m4 = *(const float4*)(mask + n * 256 + kt * 64 + jid * 4);
    float nm0 = (1.0f - m4.x) * -1e9f, nm1 = (1.0f - m4.y) * -1e9f;
    float nm2 = (1.0f - m4.z) * -1e9f, nm3 = (1.0f - m4.w) * -1e9f;
#pragma unroll
    for (int qi = 0; qi < 4; qi++) {
        int q = qt * 64 + rid * 4 + qi;
        float4 r;
        unpk(acc[qi][0], r.x, r.y);
        unpk(acc[qi][1], r.z, r.w);
        r.x += nm0; r.y += nm1; r.z += nm2; r.w += nm3;
        *(float4*)&g_base[((size_t)((n * 8 + h) * 256 + q)) * 256 + kt * 64 + jid * 4] = r;
    }
}

// ---- kC: coalesced rel stream + exchange reduce + softmax + fused attn@v ----
__global__ void __launch_bounds__(256, 2)
kC(const float* __restrict__ rel) {
    __shared__ float eng[2 * 8 * 260];
    const int n = blockIdx.y;
    const int q0 = blockIdx.x * 2;
    const int tid = threadIdx.x;
    const int w = tid >> 5, l = tid & 31;
    const bool b3 = (l & 8) != 0;
    const bool b2v = (l & 4) != 0;
    const int head = (l >> 4) + (b3 ? 4 : 0) + (b2v ? 2 : 0);

#pragma unroll
    for (int ii = 0; ii < 4; ii++) {
        int flat = ii * 256 + tid;
        int qi = flat >> 9, h = (flat >> 6) & 7, k4 = flat & 63;
        float4 v = *(const float4*)(g_base +
            ((size_t)((n * 8 + h) * 256 + q0 + qi)) * 256 + k4 * 4);
        float* e = &eng[(qi * 8 + h) * 260 + k4 * 4];
        e[0] = v.x; e[1] = v.y; e[2] = v.z; e[3] = v.w;
    }
    ulonglong2 areg[2][4];
#pragma unroll
    for (int q = 0; q < 2; q++)
#pragma unroll
        for (int u = 0; u < 4; u++)
            areg[q][u] = *(const ulonglong2*)(g_a +
                (size_t)(n * 256 + q0 + q) * 512 + u * 128 + l * 4);
    __syncthreads();

    const float* relb = rel + ((size_t)(n * 256 + q0)) * 256 * 512 + l * 4;
    const float* bbas = g_b + (size_t)n * 256 * 512 + l * 4;

    for (int t = 0; t < 32; t++) {
        const int k = t * 8 + w;
        const float* brow = bbas + (size_t)k * 512;
        const float* r0p  = relb + (size_t)k * 512;
        const float* r1p  = r0p + 256 * 512;
        ulonglong2 B[4], R0[4], R1[4];
#pragma unroll
        for (int u = 0; u < 4; u++) B[u]  = *(const ulonglong2*)(brow + u * 128);
#pragma unroll
        for (int u = 0; u < 4; u++) R0[u] = *(const ulonglong2*)(r0p + u * 128);
#pragma unroll
        for (int u = 0; u < 4; u++) R1[u] = *(const ulonglong2*)(r1p + u * 128);

        float s0[4], s1[4];
#pragma unroll
        for (int u = 0; u < 4; u++) {
            ull c0 = add2(areg[0][u].x, B[u].x);
            ull c1 = add2(areg[0][u].y, B[u].y);
            ull P  = fma2(R0[u].x, c0, 0ull);
            P      = fma2(R0[u].y, c1, P);
            s0[u] = lohi(P);
            ull d0 = add2(areg[1][u].x, B[u].x);
            ull d1 = add2(areg[1][u].y, B[u].y);
            ull Q  = fma2(R1[u].x, d0, 0ull);
            Q      = fma2(R1[u].y, d1, Q);
            s1[u] = lohi(Q);
        }
        float f, g;
        {
            float t0 = __shfl_xor_sync(0xffffffffu, s0[0], 8);
            float t1 = __shfl_xor_sync(0xffffffffu, s0[1], 8);
            float t2 = __shfl_xor_sync(0xffffffffu, s0[2], 8);
            float t3 = __shfl_xor_sync(0xffffffffu, s0[3], 8);
            float e0 = b3 ? (s0[2] + t2) : (s0[0] + t0);
            float e1 = b3 ? (s0[3] + t3) : (s0[1] + t1);
            float u0 = __shfl_xor_sync(0xffffffffu, e0, 4);
            float u1 = __shfl_xor_sync(0xffffffffu, e1, 4);
            f = b2v ? (e1 + u1) : (e0 + u0);
            f += __shfl_xor_sync(0xffffffffu, f, 1);
            f += __shfl_xor_sync(0xffffffffu, f, 2);
        }
        {
            float t0 = __shfl_xor_sync(0xffffffffu, s1[0], 8);
            float t1 = __shfl_xor_sync(0xffffffffu, s1[1], 8);
            float t2 = __shfl_xor_sync(0xffffffffu, s1[2], 8);
            float t3 = __shfl_xor_sync(0xffffffffu, s1[3], 8);
            float e0 = b3 ? (s1[2] + t2) : (s1[0] + t0);
            float e1 = b3 ? (s1[3] + t3) : (s1[1] + t1);
            float u0 = __shfl_xor_sync(0xffffffffu, e0, 4);
            float u1 = __shfl_xor_sync(0xffffffffu, e1, 4);
            g = b2v ? (e1 + u1) : (e0 + u0);
            g += __shfl_xor_sync(0xffffffffu, g, 1);
            g += __shfl_xor_sync(0xffffffffu, g, 2);
        }
        if ((l & 3) == 0) {
            eng[(0 * 8 + head) * 260 + k] += f;
            eng[(1 * 8 + head) * 260 + k] += g;
        }
    }
    __syncthreads();

#pragma unroll
    for (int qi = 0; qi < 2; qi++) {
        float v[8];
        float m = -1e30f;
#pragma unroll
        for (int j = 0; j < 8; j++) {
            v[j] = eng[(qi * 8 + w) * 260 + l + 32 * j];
            m = fmaxf(m, v[j]);
        }
#pragma unroll
        for (int off = 16; off; off >>= 1)
            m = fmaxf(m, __shfl_xor_sync(0xffffffffu, m, off));
        float s = 0.f;
#pragma unroll
        for (int j = 0; j < 8; j++) {
            v[j] = __expf(v[j] - m);
            s += v[j];
        }
#pragma unroll
        for (int off = 16; off; off >>= 1)
            s += __shfl_xor_sync(0xffffffffu, s, off);
        float inv = 1.0f / s;
#pragma unroll
        for (int j = 0; j < 8; j++)
            eng[(qi * 8 + w) * 260 + l + 32 * j] = v[j] * inv;
    }
    __syncwarp();

    ull acc0 = 0, acc1 = 0;
    const float* vpb = g_vp + (size_t)n * 256 * 512 + w * 64 + 2 * l;
    const float* p0 = &eng[(0 * 8 + w) * 260];
    const float* p1 = &eng[(1 * 8 + w) * 260];
#pragma unroll 8
    for (int k = 0; k < 256; k++) {
        ull v2 = *(const ull*)(vpb + (size_t)k * 512);
        acc0 = fma2(pack2(p0[k], p0[k]), v2, acc0);
        acc1 = fma2(pack2(p1[k], p1[k]), v2, acc1);
    }
    *(ull*)(g_outh + ((size_t)(n * 256 + q0))     * 512 + w * 64 + 2 * l) = acc0;
    *(ull*)(g_outh + ((size_t)(n * 256 + q0 + 1)) * 512 + w * 64 + 2 * l) = acc1;
}

// ---- kE: out += outh @ Wout^T (full split-K, 64-col chunk per block) ----
__global__ void __launch_bounds__(256)
kE(const float* __restrict__ Wout, float* __restrict__ out) {
    __shared__ float As[64][68];   // [m][row'] transposed+swizzled
    __shared__ float Bs[64][68];   // [m][col'] transposed+swizzled
    const int rt = blockIdx.x, jt = blockIdx.y, mt = blockIdx.z;
    const int tid = threadIdx.x;
    const int jid = tid & 15, rid = tid >> 4;

    ull acc[4][2];
#pragma unroll
    for (int qi = 0; qi < 4; qi++) { acc[qi][0] = 0; acc[qi][1] = 0; }

#pragma unroll
    for (int ii = 0; ii < 8; ii++) {
        int flat = ii * 256 + tid;
        int arr = flat >> 10;                 // 0 = A (outh), 1 = B (Wout)
        int r = (flat >> 4) & 63;
        int c4 = flat & 15;
        const float* src = arr
            ? Wout   + (size_t)(jt * 64 + r) * 512
            : g_outh + (size_t)(rt * 64 + r) * 512;
        float4 v = *(const float4*)(src + mt * 64 + c4 * 4);
        float* dst = arr ? &Bs[0][0] : &As[0][0];
        float vv[4] = {v.x, v.y, v.z, v.w};
#pragma unroll
        for (int i = 0; i < 4; i++) {
            int c = c4 * 4 + i;
            dst[c * 68 + ((((r >> 2) ^ (c & 15)) << 2) | (r & 3))] = vv[i];
        }
    }
    __syncthreads();
#pragma unroll 4
    for (int c = 0; c < 64; c++) {
        float4 aq = *(const float4*)&As[c][(rid ^ (c & 15)) << 2];
        ulonglong2 bk = *(const ulonglong2*)&Bs[c][(jid ^ (c & 15)) << 2];
        float a4[4] = {aq.x, aq.y, aq.z, aq.w};
#pragma unroll
        for (int qi = 0; qi < 4; qi++) {
            ull a2 = pack2(a4[qi], a4[qi]);
            acc[qi][0] = fma2(a2, bk.x, acc[qi][0]);
            acc[qi][1] = fma2(a2, bk.y, acc[qi][1]);
        }
    }
    int col = jt * 64 + jid * 4;
#pragma unroll
    for (int qi = 0; qi < 4; qi++) {
        int row = rt * 64 + rid * 4 + qi;
        float r0, r1, r2, r3;
        unpk(acc[qi][0], r0, r1);
        unpk(acc[qi][1], r2, r3);
        float* o = out + (size_t)row * 512 + col;
        atomicAdd(o + 0, r0);
        atomicAdd(o + 1, r1);
        atomicAdd(o + 2, r2);
        atomicAdd(o + 3, r3);
    }
}

extern "C" void kernel_launch(void* const* d_in, const int* in_sizes, int n_in,
                              void* d_out, int out_size) {
    const float* values = (const float*)d_in[0];
    const float* keys   = (const float*)d_in[1];
    const float* query  = (const float*)d_in[2];
    const float* pos    = (const float*)d_in[3];
    const float* rel    = (const float*)d_in[4];
    const float* mask   = (const float*)d_in[5];
    const float* Wv   = (const float*)d_in[6];
    const float* Wk   = (const float*)d_in[7];
    const float* Wq   = (const float*)d_in[8];
    const float* Wpq  = (const float*)d_in[9];
    const float* Wpk  = (const float*)d_in[10];
    const float* Wrk  = (const float*)d_in[11];
    const float* Wrq  = (const float*)d_in[12];
    const float* Wout = (const float*)d_in[13];
    const float* bout = (const float*)d_in[14];
    float* out = (float*)d_out;

    kA1<<<dim3(8, 8, 5), 256>>>(query, keys, pos, values, Wq, Wk, Wpq, Wpk, Wv);
    kBA2<<<dim3(24, 8, 2), 256>>>(mask, bout, out, Wrk, Wrq);
    kC<<<dim3(LL / 2, NB), 256>>>(rel);
    kE<<<dim3(8, 8, 8), 256>>>(Wout, out);
}

// round 11
// speedup vs baseline: 1.0622x; 1.0622x over previous
#include <cuda_runtime.h>
#include <cstdint>

#define NB 2
#define LL 256
#define HH 8
#define DD 64
#define EE 512
#define INVS 0.70710678118654752440f

typedef unsigned long long ull;

__device__ __forceinline__ ull fma2(ull a, ull b, ull c) {
    ull d;
    asm("fma.rn.f32x2 %0, %1, %2, %3;" : "=l"(d) : "l"(a), "l"(b), "l"(c));
    return d;
}
__device__ __forceinline__ ull add2(ull a, ull b) {
    ull d;
    asm("add.rn.f32x2 %0, %1, %2;" : "=l"(d) : "l"(a), "l"(b));
    return d;
}
__device__ __forceinline__ ull pack2(float x, float y) {
    ull d;
    asm("mov.b64 %0, {%1, %2};" : "=l"(d) : "r"(__float_as_uint(x)), "r"(__float_as_uint(y)));
    return d;
}
__device__ __forceinline__ float lohi(ull s) {
    unsigned lo, hi;
    asm("mov.b64 {%0, %1}, %2;" : "=r"(lo), "=r"(hi) : "l"(s));
    return __uint_as_float(lo) + __uint_as_float(hi);
}
__device__ __forceinline__ void unpk(ull s, float& a, float& b) {
    unsigned lo, hi;
    asm("mov.b64 {%0, %1}, %2;" : "=r"(lo), "=r"(hi) : "l"(s));
    a = __uint_as_float(lo);
    b = __uint_as_float(hi);
}

// ---- scratch ----
__device__ float g_qm[NB * LL * EE];   // q @ Wq^T * INVS
__device__ float g_k [NB * LL * EE];   // k @ Wk^T
__device__ float g_pq[NB * LL * EE];   // p @ Wpq^T * INVS
__device__ float g_pk[NB * LL * EE];   // p @ Wpk^T
__device__ float g_a [NB * LL * EE];   // qm @ Wrk  (INVS via qm)
__device__ float g_b [NB * LL * EE];   // (k' @ Wrq) * INVS
__device__ float g_vp[NB * LL * EE];   // v @ Wv^T
__device__ float g_base[NB * HH * LL * LL];
__device__ float g_outh[NB * LL * EE];

// ---- kA: per-head chained GEMMs. grid (rowtile 8, head 8, group 4) ----
__global__ void __launch_bounds__(256)
kA(const float* __restrict__ query, const float* __restrict__ keys,
   const float* __restrict__ pos,   const float* __restrict__ values,
   const float* __restrict__ Wq,  const float* __restrict__ Wk,
   const float* __restrict__ Wpq, const float* __restrict__ Wpk,
   const float* __restrict__ Wrk, const float* __restrict__ Wrq,
   const float* __restrict__ Wv) {
    __shared__ float Xs[64][68];
    __shared__ float Ys[64][68];
    __shared__ float W1s[64][64];
    __shared__ float W2s[64][64];
    const int rt = blockIdx.x, h = blockIdx.y, z = blockIdx.z;
    const int tid = threadIdx.x;
    const int cid = tid & 15, rid = tid >> 4;

    const float* src = (z == 0) ? query : (z == 1) ? keys : (z == 2) ? pos : values;
    const float* W1  = (z == 0) ? Wq    : (z == 1) ? Wk   : (z == 2) ? Wpq : Wv;
    const float* W2  = (z == 0) ? Wrk   : (z == 1) ? Wrq  : Wpk;

#pragma unroll
    for (int ii = 0; ii < 4; ii++) {
        int flat = ii * 256 + tid;
        int r = flat >> 4, c4 = flat & 15;
        *(float4*)&Xs[r][c4 * 4] =
            *(const float4*)(src + (size_t)(rt * 64 + r) * 512 + h * 64 + c4 * 4);
    }
#pragma unroll
    for (int ii = 0; ii < 4; ii++) {
        int flat = ii * 256 + tid;
        int i = flat >> 4, m4 = flat & 15;
        float4 wv = *(const float4*)(W1 + (size_t)i * 64 + m4 * 4);
        float w4[4] = {wv.x, wv.y, wv.z, wv.w};
#pragma unroll
        for (int j = 0; j < 4; j++) {
            int m = m4 * 4 + j;
            W1s[m][(((i >> 2) ^ (m & 15)) << 2) + (i & 3)] = w4[j];
        }
    }
    if (z < 2) {
#pragma unroll
        for (int ii = 0; ii < 4; ii++) {
            int flat = ii * 256 + tid;
            int i = flat >> 4, e4 = flat & 15;
            *(float4*)&W2s[i][e4 * 4] = *(const float4*)(W2 + (size_t)i * 64 + e4 * 4);
        }
    } else if (z == 2) {
#pragma unroll
        for (int ii = 0; ii < 4; ii++) {
            int flat = ii * 256 + tid;
            int i = flat >> 4, m4 = flat & 15;
            float4 wv = *(const float4*)(W2 + (size_t)i * 64 + m4 * 4);
            float w4[4] = {wv.x, wv.y, wv.z, wv.w};
#pragma unroll
            for (int j = 0; j < 4; j++) {
                int m = m4 * 4 + j;
                W2s[m][(((i >> 2) ^ (m & 15)) << 2) + (i & 3)] = w4[j];
            }
        }
    }
    __syncthreads();

    ull acc[4][2];
#pragma unroll
    for (int rj = 0; rj < 4; rj++) { acc[rj][0] = 0; acc[rj][1] = 0; }
#pragma unroll 4
    for (int m = 0; m < 64; m++) {
        ulonglong2 wv = *(const ulonglong2*)&W1s[m][(cid ^ (m & 15)) << 2];
#pragma unroll
        for (int rj = 0; rj < 4; rj++) {
            float xa = Xs[rj * 16 + rid][m];
            ull xa2 = pack2(xa, xa);
            acc[rj][0] = fma2(xa2, wv.x, acc[rj][0]);
            acc[rj][1] = fma2(xa2, wv.y, acc[rj][1]);
        }
    }
    float s1 = (z == 0 || z == 2) ? INVS : 1.0f;
    float* out1 = (z == 0) ? g_qm : (z == 1) ? g_k : (z == 2) ? g_pq : g_vp;
    ull s1v = pack2(s1, s1);
#pragma unroll
    for (int rj = 0; rj < 4; rj++) {
        int row = rj * 16 + rid;
        ulonglong2 o;
        o.x = fma2(acc[rj][0], s1v, 0ull);
        o.y = fma2(acc[rj][1], s1v, 0ull);
        *(ulonglong2*)(out1 + (size_t)(rt * 64 + row) * 512 + h * 64 + cid * 4) = o;
        *(ulonglong2*)&Ys[row][cid * 4] = o;
    }
    if (z == 3) return;
    __syncthreads();

    ull acc2[4][2];
#pragma unroll
    for (int rj = 0; rj < 4; rj++) { acc2[rj][0] = 0; acc2[rj][1] = 0; }
    if (z < 2) {
#pragma unroll 4
        for (int i = 0; i < 64; i++) {
            ulonglong2 wv = *(const ulonglong2*)&W2s[i][cid * 4];
#pragma unroll
            for (int rj = 0; rj < 4; rj++) {
                float ya = Ys[rj * 16 + rid][i];
                ull ya2 = pack2(ya, ya);
                acc2[rj][0] = fma2(ya2, wv.x, acc2[rj][0]);
                acc2[rj][1] = fma2(ya2, wv.y, acc2[rj][1]);
            }
        }
    } else {
#pragma unroll 4
        for (int m = 0; m < 64; m++) {
            ulonglong2 wv = *(const ulonglong2*)&W2s[m][(cid ^ (m & 15)) << 2];
#pragma unroll
            for (int rj = 0; rj < 4; rj++) {
                float xa = Xs[rj * 16 + rid][m];
                ull xa2 = pack2(xa, xa);
                acc2[rj][0] = fma2(xa2, wv.x, acc2[rj][0]);
                acc2[rj][1] = fma2(xa2, wv.y, acc2[rj][1]);
            }
        }
    }
    float s2 = (z == 1) ? INVS : 1.0f;
    float* out2 = (z == 0) ? g_a : (z == 1) ? g_b : g_pk;
    ull s2v = pack2(s2, s2);
#pragma unroll
    for (int rj = 0; rj < 4; rj++) {
        int row = rj * 16 + rid;
        ulonglong2 o;
        o.x = fma2(acc2[rj][0], s2v, 0ull);
        o.y = fma2(acc2[rj][1], s2v, 0ull);
        *(ulonglong2*)(out2 + (size_t)(rt * 64 + row) * 512 + h * 64 + cid * 4) = o;
    }
}

// ---- kB: base = (qm|pq).(k'|pk)^T + mask; also writes bias rows into out ----
__global__ void __launch_bounds__(256)
kB(const float* __restrict__ mask, const float* __restrict__ bout,
   float* __restrict__ out) {
    __shared__ float As[64][68];
    __shared__ float Bs[64][68];
    const int qt = blockIdx.x >> 2, kt = blockIdx.x & 3;
    const int h = blockIdx.y, n = blockIdx.z;
    const int tid = threadIdx.x;
    const int jid = tid & 15, rid = tid >> 4;

    // bias init for out (kE accumulates atomically afterwards, same graph)
    {
        int lb = blockIdx.x + 16 * blockIdx.y + 128 * blockIdx.z;   // 0..255
        int row = 2 * lb + (tid >> 7);
        int c4 = (tid & 127) * 4;
        *(float4*)(out + (size_t)row * 512 + c4) = *(const float4*)(bout + c4);
    }

    ull acc[4][2];
#pragma unroll
    for (int qi = 0; qi < 4; qi++) { acc[qi][0] = 0; acc[qi][1] = 0; }

#pragma unroll
    for (int s = 0; s < 2; s++) {
        __syncthreads();
        const float* Aop = s ? g_pq : g_qm;
        const float* Bop = s ? g_pk : g_k;
#pragma unroll
        for (int ii = 0; ii < 8; ii++) {
            int flat = ii * 256 + tid;
            int arr = flat >> 10;
            int r = (flat >> 4) & 63;
            int c4 = flat & 15;
            const float* src = arr
                ? Bop + (size_t)(n * 256 + kt * 64 + r) * 512
                : Aop + (size_t)(n * 256 + qt * 64 + r) * 512;
            float4 v = *(const float4*)(src + h * 64 + c4 * 4);
            float* dst = arr ? &Bs[0][0] : &As[0][0];
            float vv[4] = {v.x, v.y, v.z, v.w};
#pragma unroll
            for (int i = 0; i < 4; i++) {
                int c = c4 * 4 + i;
                dst[c * 68 + ((((r >> 2) ^ (c & 15)) << 2) | (r & 3))] = vv[i];
            }
        }
        __syncthreads();
#pragma unroll 4
        for (int c = 0; c < 64; c++) {
            float4 aq = *(const float4*)&As[c][(rid ^ (c & 15)) << 2];
            ulonglong2 bk = *(const ulonglong2*)&Bs[c][(jid ^ (c & 15)) << 2];
            float a4[4] = {aq.x, aq.y, aq.z, aq.w};
#pragma unroll
            for (int qi = 0; qi < 4; qi++) {
                ull a2 = pack2(a4[qi], a4[qi]);
                acc[qi][0] = fma2(a2, bk.x, acc[qi][0]);
                acc[qi][1] = fma2(a2, bk.y, acc[qi][1]);
            }
        }
    }
    float4 m4 = *(const float4*)(mask + n * 256 + kt * 64 + jid * 4);
    float nm0 = (1.0f - m4.x) * -1e9f, nm1 = (1.0f - m4.y) * -1e9f;
    float nm2 = (1.0f - m4.z) * -1e9f, nm3 = (1.0f - m4.w) * -1e9f;
#pragma unroll
    for (int qi = 0; qi < 4; qi++) {
        int q = qt * 64 + rid * 4 + qi;
        float4 r;
        unpk(acc[qi][0], r.x, r.y);
        unpk(acc[qi][1], r.z, r.w);
        r.x += nm0; r.y += nm1; r.z += nm2; r.w += nm3;
        *(float4*)&g_base[((size_t)((n * 8 + h) * 256 + q)) * 256 + kt * 64 + jid * 4] = r;
    }
}

// ---- kC: coalesced rel stream + exchange reduce + softmax + fused attn@v ----
__global__ void __launch_bounds__(256, 2)
kC(const float* __restrict__ rel) {
    __shared__ float eng[2 * 8 * 260];
    const int n = blockIdx.y;
    const int q0 = blockIdx.x * 2;
    const int tid = threadIdx.x;
    const int w = tid >> 5, l = tid & 31;
    const bool b3 = (l & 8) != 0;
    const bool b2v = (l & 4) != 0;
    const int head = (l >> 4) + (b3 ? 4 : 0) + (b2v ? 2 : 0);

#pragma unroll
    for (int ii = 0; ii < 4; ii++) {
        int flat = ii * 256 + tid;
        int qi = flat >> 9, h = (flat >> 6) & 7, k4 = flat & 63;
        float4 v = *(const float4*)(g_base +
            ((size_t)((n * 8 + h) * 256 + q0 + qi)) * 256 + k4 * 4);
        float* e = &eng[(qi * 8 + h) * 260 + k4 * 4];
        e[0] = v.x; e[1] = v.y; e[2] = v.z; e[3] = v.w;
    }
    ulonglong2 areg[2][4];
#pragma unroll
    for (int q = 0; q < 2; q++)
#pragma unroll
        for (int u = 0; u < 4; u++)
            areg[q][u] = *(const ulonglong2*)(g_a +
                (size_t)(n * 256 + q0 + q) * 512 + u * 128 + l * 4);
    __syncthreads();

    const float* relb = rel + ((size_t)(n * 256 + q0)) * 256 * 512 + l * 4;
    const float* bbas = g_b + (size_t)n * 256 * 512 + l * 4;

    for (int t = 0; t < 32; t++) {
        const int k = t * 8 + w;
        const float* brow = bbas + (size_t)k * 512;
        const float* r0p  = relb + (size_t)k * 512;
        const float* r1p  = r0p + 256 * 512;
        ulonglong2 B[4], R0[4], R1[4];
#pragma unroll
        for (int u = 0; u < 4; u++) B[u]  = *(const ulonglong2*)(brow + u * 128);
#pragma unroll
        for (int u = 0; u < 4; u++) R0[u] = *(const ulonglong2*)(r0p + u * 128);
#pragma unroll
        for (int u = 0; u < 4; u++) R1[u] = *(const ulonglong2*)(r1p + u * 128);

        float s0[4], s1[4];
#pragma unroll
        for (int u = 0; u < 4; u++) {
            ull c0 = add2(areg[0][u].x, B[u].x);
            ull c1 = add2(areg[0][u].y, B[u].y);
            ull P  = fma2(R0[u].x, c0, 0ull);
            P      = fma2(R0[u].y, c1, P);
            s0[u] = lohi(P);
            ull d0 = add2(areg[1][u].x, B[u].x);
            ull d1 = add2(areg[1][u].y, B[u].y);
            ull Q  = fma2(R1[u].x, d0, 0ull);
            Q      = fma2(R1[u].y, d1, Q);
            s1[u] = lohi(Q);
        }
        float f, g;
        {
            float t0 = __shfl_xor_sync(0xffffffffu, s0[0], 8);
            float t1 = __shfl_xor_sync(0xffffffffu, s0[1], 8);
            float t2 = __shfl_xor_sync(0xffffffffu, s0[2], 8);
            float t3 = __shfl_xor_sync(0xffffffffu, s0[3], 8);
            float e0 = b3 ? (s0[2] + t2) : (s0[0] + t0);
            float e1 = b3 ? (s0[3] + t3) : (s0[1] + t1);
            float u0 = __shfl_xor_sync(0xffffffffu, e0, 4);
            float u1 = __shfl_xor_sync(0xffffffffu, e1, 4);
            f = b2v ? (e1 + u1) : (e0 + u0);
            f += __shfl_xor_sync(0xffffffffu, f, 1);
            f += __shfl_xor_sync(0xffffffffu, f, 2);
        }
        {
            float t0 = __shfl_xor_sync(0xffffffffu, s1[0], 8);
            float t1 = __shfl_xor_sync(0xffffffffu, s1[1], 8);
            float t2 = __shfl_xor_sync(0xffffffffu, s1[2], 8);
            float t3 = __shfl_xor_sync(0xffffffffu, s1[3], 8);
            float e0 = b3 ? (s1[2] + t2) : (s1[0] + t0);
            float e1 = b3 ? (s1[3] + t3) : (s1[1] + t1);
            float u0 = __shfl_xor_sync(0xffffffffu, e0, 4);
            float u1 = __shfl_xor_sync(0xffffffffu, e1, 4);
            g = b2v ? (e1 + u1) : (e0 + u0);
            g += __shfl_xor_sync(0xffffffffu, g, 1);
            g += __shfl_xor_sync(0xffffffffu, g, 2);
        }
        if ((l & 3) == 0) {
            eng[(0 * 8 + head) * 260 + k] += f;
            eng[(1 * 8 + head) * 260 + k] += g;
        }
    }
    __syncthreads();

#pragma unroll
    for (int qi = 0; qi < 2; qi++) {
        float v[8];
        float m = -1e30f;
#pragma unroll
        for (int j = 0; j < 8; j++) {
            v[j] = eng[(qi * 8 + w) * 260 + l + 32 * j];
            m = fmaxf(m, v[j]);
        }
#pragma unroll
        for (int off = 16; off; off >>= 1)
            m = fmaxf(m, __shfl_xor_sync(0xffffffffu, m, off));
        float s = 0.f;
#pragma unroll
        for (int j = 0; j < 8; j++) {
            v[j] = __expf(v[j] - m);
            s += v[j];
        }
#pragma unroll
        for (int off = 16; off; off >>= 1)
            s += __shfl_xor_sync(0xffffffffu, s, off);
        float inv = 1.0f / s;
#pragma unroll
        for (int j = 0; j < 8; j++)
            eng[(qi * 8 + w) * 260 + l + 32 * j] = v[j] * inv;
    }
    __syncwarp();

    ull acc0 = 0, acc1 = 0;
    const float* vpb = g_vp + (size_t)n * 256 * 512 + w * 64 + 2 * l;
    const float* p0 = &eng[(0 * 8 + w) * 260];
    const float* p1 = &eng[(1 * 8 + w) * 260];
#pragma unroll 8
    for (int k = 0; k < 256; k++) {
        ull v2 = *(const ull*)(vpb + (size_t)k * 512);
        acc0 = fma2(pack2(p0[k], p0[k]), v2, acc0);
        acc1 = fma2(pack2(p1[k], p1[k]), v2, acc1);
    }
    *(ull*)(g_outh + ((size_t)(n * 256 + q0))     * 512 + w * 64 + 2 * l) = acc0;
    *(ull*)(g_outh + ((size_t)(n * 256 + q0 + 1)) * 512 + w * 64 + 2 * l) = acc1;
}

// ---- kE: out += outh @ Wout^T. 64x128 tile, 4x8/thread, split-K 64/block ----
// dyn smem: As[64][68] + Bs[2][64][68] = 13056 floats = 52224 B
__global__ void __launch_bounds__(256)
kE(const float* __restrict__ Wout, float* __restrict__ out) {
    extern __shared__ float sm[];
    float* As = sm;                    // [c][r'] 64x68
    float* Bs = sm + 64 * 68;          // [g][c][j'] 2x64x68
    const int rt = blockIdx.x, jt = blockIdx.y, mt = blockIdx.z;
    const int tid = threadIdx.x;
    const int jid = tid & 15, rid = tid >> 4;

    // stage A (outh rows rt*64.., k-cols mt*64..): transposed+swizzled
#pragma unroll
    for (int ii = 0; ii < 4; ii++) {
        int flat = ii * 256 + tid;
        int r = flat >> 4, c4 = flat & 15;
        float4 v = *(const float4*)(g_outh +
            (size_t)(rt * 64 + r) * 512 + mt * 64 + c4 * 4);
        float vv[4] = {v.x, v.y, v.z, v.w};
#pragma unroll
        for (int i = 0; i < 4; i++) {
            int c = c4 * 4 + i;
            As[c * 68 + ((((r >> 2) ^ (c & 15)) << 2) | (r & 3))] = vv[i];
        }
    }
    // stage B (Wout rows jt*128..+128, k-cols mt*64..): transposed+swizzled, 2 groups
#pragma unroll
    for (int ii = 0; ii < 8; ii++) {
        int flat = ii * 256 + tid;
        int r128 = flat >> 4, c4 = flat & 15;
        int g = r128 >> 6, r = r128 & 63;
        float4 v = *(const float4*)(Wout +
            (size_t)(jt * 128 + r128) * 512 + mt * 64 + c4 * 4);
        float vv[4] = {v.x, v.y, v.z, v.w};
#pragma unroll
        for (int i = 0; i < 4; i++) {
            int c = c4 * 4 + i;
            Bs[(g * 64 + c) * 68 + ((((r >> 2) ^ (c & 15)) << 2) | (r & 3))] = vv[i];
        }
    }
    __syncthreads();

    ull acc[4][2][2];
#pragma unroll
    for (int qi = 0; qi < 4; qi++)
#pragma unroll
        for (int g = 0; g < 2; g++) { acc[qi][g][0] = 0; acc[qi][g][1] = 0; }

#pragma unroll 4
    for (int c = 0; c < 64; c++) {
        float4 aq = *(const float4*)&As[c * 68 + ((rid ^ (c & 15)) << 2)];
        ulonglong2 bk0 = *(const ulonglong2*)&Bs[c * 68 + ((jid ^ (c & 15)) << 2)];
        ulonglong2 bk1 = *(const ulonglong2*)&Bs[(64 + c) * 68 + ((jid ^ (c & 15)) << 2)];
        float a4[4] = {aq.x, aq.y, aq.z, aq.w};
#pragma unroll
        for (int qi = 0; qi < 4; qi++) {
            ull a2 = pack2(a4[qi], a4[qi]);
            acc[qi][0][0] = fma2(a2, bk0.x, acc[qi][0][0]);
            acc[qi][0][1] = fma2(a2, bk0.y, acc[qi][0][1]);
            acc[qi][1][0] = fma2(a2, bk1.x, acc[qi][1][0]);
            acc[qi][1][1] = fma2(a2, bk1.y, acc[qi][1][1]);
        }
    }
#pragma unroll
    for (int qi = 0; qi < 4; qi++) {
        int row = rt * 64 + rid * 4 + qi;
#pragma unroll
        for (int g = 0; g < 2; g++) {
            int col = jt * 128 + g * 64 + jid * 4;
            float r0, r1, r2, r3;
            unpk(acc[qi][g][0], r0, r1);
            unpk(acc[qi][g][1], r2, r3);
            float* o = out + (size_t)row * 512 + col;
            atomicAdd(o + 0, r0);
            atomicAdd(o + 1, r1);
            atomicAdd(o + 2, r2);
            atomicAdd(o + 3, r3);
        }
    }
}

extern "C" void kernel_launch(void* const* d_in, const int* in_sizes, int n_in,
                              void* d_out, int out_size) {
    const float* values = (const float*)d_in[0];
    const float* keys   = (const float*)d_in[1];
    const float* query  = (const float*)d_in[2];
    const float* pos    = (const float*)d_in[3];
    const float* rel    = (const float*)d_in[4];
    const float* mask   = (const float*)d_in[5];
    const float* Wv   = (const float*)d_in[6];
    const float* Wk   = (const float*)d_in[7];
    const float* Wq   = (const float*)d_in[8];
    const float* Wpq  = (const float*)d_in[9];
    const float* Wpk  = (const float*)d_in[10];
    const float* Wrk  = (const float*)d_in[11];
    const float* Wrq  = (const float*)d_in[12];
    const float* Wout = (const float*)d_in[13];
    const float* bout = (const float*)d_in[14];
    float* out = (float*)d_out;

    static bool attr_done = false;
    if (!attr_done) {
        cudaFuncSetAttribute(kE, cudaFuncAttributeMaxDynamicSharedMemorySize, 52224);
        attr_done = true;
    }

    kA<<<dim3(8, 8, 4), 256>>>(query, keys, pos, values,
                               Wq, Wk, Wpq, Wpk, Wrk, Wrq, Wv);
    kB<<<dim3(16, HH, NB), 256>>>(mask, bout, out);
    kC<<<dim3(LL / 2, NB), 256>>>(rel);
    kE<<<dim3(8, 4, 8), 256, 52224>>>(Wout, out);
}

// round 12
// speedup vs baseline: 1.1650x; 1.0968x over previous
#include <cuda_runtime.h>
#include <cstdint>

#define NB 2
#define LL 256
#define HH 8
#define DD 64
#define EE 512
#define INVS 0.70710678118654752440f

typedef unsigned long long ull;

__device__ __forceinline__ ull fma2(ull a, ull b, ull c) {
    ull d;
    asm("fma.rn.f32x2 %0, %1, %2, %3;" : "=l"(d) : "l"(a), "l"(b), "l"(c));
    return d;
}
__device__ __forceinline__ ull add2(ull a, ull b) {
    ull d;
    asm("add.rn.f32x2 %0, %1, %2;" : "=l"(d) : "l"(a), "l"(b));
    return d;
}
__device__ __forceinline__ ull pack2(float x, float y) {
    ull d;
    asm("mov.b64 %0, {%1, %2};" : "=l"(d) : "r"(__float_as_uint(x)), "r"(__float_as_uint(y)));
    return d;
}
__device__ __forceinline__ float lohi(ull s) {
    unsigned lo, hi;
    asm("mov.b64 {%0, %1}, %2;" : "=r"(lo), "=r"(hi) : "l"(s));
    return __uint_as_float(lo) + __uint_as_float(hi);
}
__device__ __forceinline__ void unpk(ull s, float& a, float& b) {
    unsigned lo, hi;
    asm("mov.b64 {%0, %1}, %2;" : "=r"(lo), "=r"(hi) : "l"(s));
    a = __uint_as_float(lo);
    b = __uint_as_float(hi);
}

// ---- scratch ----
__device__ float g_qm[NB * LL * EE];   // q @ Wq^T * INVS
__device__ float g_k [NB * LL * EE];   // k @ Wk^T
__device__ float g_pq[NB * LL * EE];   // p @ Wpq^T * INVS
__device__ float g_pk[NB * LL * EE];   // p @ Wpk^T
__device__ float g_a [NB * LL * EE];   // qm @ Wrk  (INVS via qm)
__device__ float g_b [NB * LL * EE];   // (k' @ Wrq) * INVS
__device__ float g_vp[NB * LL * EE];   // v @ Wv^T
__device__ float g_base[NB * HH * LL * LL];
__device__ float g_outh[NB * LL * EE];

// ---- kA: per-head chained GEMMs. grid (rowtile 8, head 8, group 4) ----
__global__ void __launch_bounds__(256)
kA(const float* __restrict__ query, const float* __restrict__ keys,
   const float* __restrict__ pos,   const float* __restrict__ values,
   const float* __restrict__ Wq,  const float* __restrict__ Wk,
   const float* __restrict__ Wpq, const float* __restrict__ Wpk,
   const float* __restrict__ Wrk, const float* __restrict__ Wrq,
   const float* __restrict__ Wv) {
    __shared__ float Xs[64][68];
    __shared__ float Ys[64][68];
    __shared__ float W1s[64][64];
    __shared__ float W2s[64][64];
    const int rt = blockIdx.x, h = blockIdx.y, z = blockIdx.z;
    const int tid = threadIdx.x;
    const int cid = tid & 15, rid = tid >> 4;

    const float* src = (z == 0) ? query : (z == 1) ? keys : (z == 2) ? pos : values;
    const float* W1  = (z == 0) ? Wq    : (z == 1) ? Wk   : (z == 2) ? Wpq : Wv;
    const float* W2  = (z == 0) ? Wrk   : (z == 1) ? Wrq  : Wpk;

#pragma unroll
    for (int ii = 0; ii < 4; ii++) {
        int flat = ii * 256 + tid;
        int r = flat >> 4, c4 = flat & 15;
        *(float4*)&Xs[r][c4 * 4] =
            *(const float4*)(src + (size_t)(rt * 64 + r) * 512 + h * 64 + c4 * 4);
    }
#pragma unroll
    for (int ii = 0; ii < 4; ii++) {
        int flat = ii * 256 + tid;
        int i = flat >> 4, m4 = flat & 15;
        float4 wv = *(const float4*)(W1 + (size_t)i * 64 + m4 * 4);
        float w4[4] = {wv.x, wv.y, wv.z, wv.w};
#pragma unroll
        for (int j = 0; j < 4; j++) {
            int m = m4 * 4 + j;
            W1s[m][(((i >> 2) ^ (m & 15)) << 2) + (i & 3)] = w4[j];
        }
    }
    if (z < 2) {
#pragma unroll
        for (int ii = 0; ii < 4; ii++) {
            int flat = ii * 256 + tid;
            int i = flat >> 4, e4 = flat & 15;
            *(float4*)&W2s[i][e4 * 4] = *(const float4*)(W2 + (size_t)i * 64 + e4 * 4);
        }
    } else if (z == 2) {
#pragma unroll
        for (int ii = 0; ii < 4; ii++) {
            int flat = ii * 256 + tid;
            int i = flat >> 4, m4 = flat & 15;
            float4 wv = *(const float4*)(W2 + (size_t)i * 64 + m4 * 4);
            float w4[4] = {wv.x, wv.y, wv.z, wv.w};
#pragma unroll
            for (int j = 0; j < 4; j++) {
                int m = m4 * 4 + j;
                W2s[m][(((i >> 2) ^ (m & 15)) << 2) + (i & 3)] = w4[j];
            }
        }
    }
    __syncthreads();

    ull acc[4][2];
#pragma unroll
    for (int rj = 0; rj < 4; rj++) { acc[rj][0] = 0; acc[rj][1] = 0; }
#pragma unroll 4
    for (int m = 0; m < 64; m++) {
        ulonglong2 wv = *(const ulonglong2*)&W1s[m][(cid ^ (m & 15)) << 2];
#pragma unroll
        for (int rj = 0; rj < 4; rj++) {
            float xa = Xs[rj * 16 + rid][m];
            ull xa2 = pack2(xa, xa);
            acc[rj][0] = fma2(xa2, wv.x, acc[rj][0]);
            acc[rj][1] = fma2(xa2, wv.y, acc[rj][1]);
        }
    }
    float s1 = (z == 0 || z == 2) ? INVS : 1.0f;
    float* out1 = (z == 0) ? g_qm : (z == 1) ? g_k : (z == 2) ? g_pq : g_vp;
    ull s1v = pack2(s1, s1);
#pragma unroll
    for (int rj = 0; rj < 4; rj++) {
        int row = rj * 16 + rid;
        ulonglong2 o;
        o.x = fma2(acc[rj][0], s1v, 0ull);
        o.y = fma2(acc[rj][1], s1v, 0ull);
        *(ulonglong2*)(out1 + (size_t)(rt * 64 + row) * 512 + h * 64 + cid * 4) = o;
        *(ulonglong2*)&Ys[row][cid * 4] = o;
    }
    if (z == 3) return;
    __syncthreads();

    ull acc2[4][2];
#pragma unroll
    for (int rj = 0; rj < 4; rj++) { acc2[rj][0] = 0; acc2[rj][1] = 0; }
    if (z < 2) {
#pragma unroll 4
        for (int i = 0; i < 64; i++) {
            ulonglong2 wv = *(const ulonglong2*)&W2s[i][cid * 4];
#pragma unroll
            for (int rj = 0; rj < 4; rj++) {
                float ya = Ys[rj * 16 + rid][i];
                ull ya2 = pack2(ya, ya);
                acc2[rj][0] = fma2(ya2, wv.x, acc2[rj][0]);
                acc2[rj][1] = fma2(ya2, wv.y, acc2[rj][1]);
            }
        }
    } else {
#pragma unroll 4
        for (int m = 0; m < 64; m++) {
            ulonglong2 wv = *(const ulonglong2*)&W2s[m][(cid ^ (m & 15)) << 2];
#pragma unroll
            for (int rj = 0; rj < 4; rj++) {
                float xa = Xs[rj * 16 + rid][m];
                ull xa2 = pack2(xa, xa);
                acc2[rj][0] = fma2(xa2, wv.x, acc2[rj][0]);
                acc2[rj][1] = fma2(xa2, wv.y, acc2[rj][1]);
            }
        }
    }
    float s2 = (z == 1) ? INVS : 1.0f;
    float* out2 = (z == 0) ? g_a : (z == 1) ? g_b : g_pk;
    ull s2v = pack2(s2, s2);
#pragma unroll
    for (int rj = 0; rj < 4; rj++) {
        int row = rj * 16 + rid;
        ulonglong2 o;
        o.x = fma2(acc2[rj][0], s2v, 0ull);
        o.y = fma2(acc2[rj][1], s2v, 0ull);
        *(ulonglong2*)(out2 + (size_t)(rt * 64 + row) * 512 + h * 64 + cid * 4) = o;
    }
}

// ---- kB: base = (qm|pq).(k'|pk)^T + mask; also writes bias rows into out ----
__global__ void __launch_bounds__(256)
kB(const float* __restrict__ mask, const float* __restrict__ bout,
   float* __restrict__ out) {
    __shared__ float As[64][68];
    __shared__ float Bs[64][68];
    const int qt = blockIdx.x >> 2, kt = blockIdx.x & 3;
    const int h = blockIdx.y, n = blockIdx.z;
    const int tid = threadIdx.x;
    const int jid = tid & 15, rid = tid >> 4;

    // bias init for out (kE accumulates atomically afterwards, same graph)
    {
        int lb = blockIdx.x + 16 * blockIdx.y + 128 * blockIdx.z;   // 0..255
        int row = 2 * lb + (tid >> 7);
        int c4 = (tid & 127) * 4;
        *(float4*)(out + (size_t)row * 512 + c4) = *(const float4*)(bout + c4);
    }

    ull acc[4][2];
#pragma unroll
    for (int qi = 0; qi < 4; qi++) { acc[qi][0] = 0; acc[qi][1] = 0; }

#pragma unroll
    for (int s = 0; s < 2; s++) {
        __syncthreads();
        const float* Aop = s ? g_pq : g_qm;
        const float* Bop = s ? g_pk : g_k;
#pragma unroll
        for (int ii = 0; ii < 8; ii++) {
            int flat = ii * 256 + tid;
            int arr = flat >> 10;
            int r = (flat >> 4) & 63;
            int c4 = flat & 15;
            const float* src = arr
                ? Bop + (size_t)(n * 256 + kt * 64 + r) * 512
                : Aop + (size_t)(n * 256 + qt * 64 + r) * 512;
            float4 v = *(const float4*)(src + h * 64 + c4 * 4);
            float* dst = arr ? &Bs[0][0] : &As[0][0];
            float vv[4] = {v.x, v.y, v.z, v.w};
#pragma unroll
            for (int i = 0; i < 4; i++) {
                int c = c4 * 4 + i;
                dst[c * 68 + ((((r >> 2) ^ (c & 15)) << 2) | (r & 3))] = vv[i];
            }
        }
        __syncthreads();
#pragma unroll 4
        for (int c = 0; c < 64; c++) {
            float4 aq = *(const float4*)&As[c][(rid ^ (c & 15)) << 2];
            ulonglong2 bk = *(const ulonglong2*)&Bs[c][(jid ^ (c & 15)) << 2];
            float a4[4] = {aq.x, aq.y, aq.z, aq.w};
#pragma unroll
            for (int qi = 0; qi < 4; qi++) {
                ull a2 = pack2(a4[qi], a4[qi]);
                acc[qi][0] = fma2(a2, bk.x, acc[qi][0]);
                acc[qi][1] = fma2(a2, bk.y, acc[qi][1]);
            }
        }
    }
    float4 m4 = *(const float4*)(mask + n * 256 + kt * 64 + jid * 4);
    float nm0 = (1.0f - m4.x) * -1e9f, nm1 = (1.0f - m4.y) * -1e9f;
    float nm2 = (1.0f - m4.z) * -1e9f, nm3 = (1.0f - m4.w) * -1e9f;
#pragma unroll
    for (int qi = 0; qi < 4; qi++) {
        int q = qt * 64 + rid * 4 + qi;
        float4 r;
        unpk(acc[qi][0], r.x, r.y);
        unpk(acc[qi][1], r.z, r.w);
        r.x += nm0; r.y += nm1; r.z += nm2; r.w += nm3;
        *(float4*)&g_base[((size_t)((n * 8 + h) * 256 + q)) * 256 + kt * 64 + jid * 4] = r;
    }
}

// ---- kC: coalesced rel stream (evict-first) + exchange reduce + softmax + attn@v ----
__global__ void __launch_bounds__(256, 2)
kC(const float* __restrict__ rel) {
    __shared__ float eng[2 * 8 * 260];
    const int n = blockIdx.y;
    const int q0 = blockIdx.x * 2;
    const int tid = threadIdx.x;
    const int w = tid >> 5, l = tid & 31;
    const bool b3 = (l & 8) != 0;
    const bool b2v = (l & 4) != 0;
    const int head = (l >> 4) + (b3 ? 4 : 0) + (b2v ? 2 : 0);

#pragma unroll
    for (int ii = 0; ii < 4; ii++) {
        int flat = ii * 256 + tid;
        int qi = flat >> 9, h = (flat >> 6) & 7, k4 = flat & 63;
        float4 v = *(const float4*)(g_base +
            ((size_t)((n * 8 + h) * 256 + q0 + qi)) * 256 + k4 * 4);
        float* e = &eng[(qi * 8 + h) * 260 + k4 * 4];
        e[0] = v.x; e[1] = v.y; e[2] = v.z; e[3] = v.w;
    }
    ulonglong2 areg[2][4];
#pragma unroll
    for (int q = 0; q < 2; q++)
#pragma unroll
        for (int u = 0; u < 4; u++)
            areg[q][u] = *(const ulonglong2*)(g_a +
                (size_t)(n * 256 + q0 + q) * 512 + u * 128 + l * 4);
    __syncthreads();

    const float* relb = rel + ((size_t)(n * 256 + q0)) * 256 * 512 + l * 4;
    const float* bbas = g_b + (size_t)n * 256 * 512 + l * 4;

    for (int t = 0; t < 32; t++) {
        const int k = t * 8 + w;
        const float* brow = bbas + (size_t)k * 512;
        const float* r0p  = relb + (size_t)k * 512;
        const float* r1p  = r0p + 256 * 512;
        ulonglong2 B[4], R0[4], R1[4];
#pragma unroll
        for (int u = 0; u < 4; u++) B[u]  = *(const ulonglong2*)(brow + u * 128);
#pragma unroll
        for (int u = 0; u < 4; u++) R0[u] = __ldcs((const ulonglong2*)(r0p + u * 128));
#pragma unroll
        for (int u = 0; u < 4; u++) R1[u] = __ldcs((const ulonglong2*)(r1p + u * 128));

        float s0[4], s1[4];
#pragma unroll
        for (int u = 0; u < 4; u++) {
            ull c0 = add2(areg[0][u].x, B[u].x);
            ull c1 = add2(areg[0][u].y, B[u].y);
            ull P  = fma2(R0[u].x, c0, 0ull);
            P      = fma2(R0[u].y, c1, P);
            s0[u] = lohi(P);
            ull d0 = add2(areg[1][u].x, B[u].x);
            ull d1 = add2(areg[1][u].y, B[u].y);
            ull Q  = fma2(R1[u].x, d0, 0ull);
            Q      = fma2(R1[u].y, d1, Q);
            s1[u] = lohi(Q);
        }
        float f, g;
        {
            float t0 = __shfl_xor_sync(0xffffffffu, s0[0], 8);
            float t1 = __shfl_xor_sync(0xffffffffu, s0[1], 8);
            float t2 = __shfl_xor_sync(0xffffffffu, s0[2], 8);
            float t3 = __shfl_xor_sync(0xffffffffu, s0[3], 8);
            float e0 = b3 ? (s0[2] + t2) : (s0[0] + t0);
            float e1 = b3 ? (s0[3] + t3) : (s0[1] + t1);
            float u0 = __shfl_xor_sync(0xffffffffu, e0, 4);
            float u1 = __shfl_xor_sync(0xffffffffu, e1, 4);
            f = b2v ? (e1 + u1) : (e0 + u0);
            f += __shfl_xor_sync(0xffffffffu, f, 1);
            f += __shfl_xor_sync(0xffffffffu, f, 2);
        }
        {
            float t0 = __shfl_xor_sync(0xffffffffu, s1[0], 8);
            float t1 = __shfl_xor_sync(0xffffffffu, s1[1], 8);
            float t2 = __shfl_xor_sync(0xffffffffu, s1[2], 8);
            float t3 = __shfl_xor_sync(0xffffffffu, s1[3], 8);
            float e0 = b3 ? (s1[2] + t2) : (s1[0] + t0);
            float e1 = b3 ? (s1[3] + t3) : (s1[1] + t1);
            float u0 = __shfl_xor_sync(0xffffffffu, e0, 4);
            float u1 = __shfl_xor_sync(0xffffffffu, e1, 4);
            g = b2v ? (e1 + u1) : (e0 + u0);
            g += __shfl_xor_sync(0xffffffffu, g, 1);
            g += __shfl_xor_sync(0xffffffffu, g, 2);
        }
        if ((l & 3) == 0) {
            eng[(0 * 8 + head) * 260 + k] += f;
            eng[(1 * 8 + head) * 260 + k] += g;
        }
    }
    __syncthreads();

#pragma unroll
    for (int qi = 0; qi < 2; qi++) {
        float v[8];
        float m = -1e30f;
#pragma unroll
        for (int j = 0; j < 8; j++) {
            v[j] = eng[(qi * 8 + w) * 260 + l + 32 * j];
            m = fmaxf(m, v[j]);
        }
#pragma unroll
        for (int off = 16; off; off >>= 1)
            m = fmaxf(m, __shfl_xor_sync(0xffffffffu, m, off));
        float s = 0.f;
#pragma unroll
        for (int j = 0; j < 8; j++) {
            v[j] = __expf(v[j] - m);
            s += v[j];
        }
#pragma unroll
        for (int off = 16; off; off >>= 1)
            s += __shfl_xor_sync(0xffffffffu, s, off);
        float inv = 1.0f / s;
#pragma unroll
        for (int j = 0; j < 8; j++)
            eng[(qi * 8 + w) * 260 + l + 32 * j] = v[j] * inv;
    }
    __syncwarp();

    ull acc0 = 0, acc1 = 0;
    const float* vpb = g_vp + (size_t)n * 256 * 512 + w * 64 + 2 * l;
    const float* p0 = &eng[(0 * 8 + w) * 260];
    const float* p1 = &eng[(1 * 8 + w) * 260];
#pragma unroll 8
    for (int k = 0; k < 256; k++) {
        ull v2 = *(const ull*)(vpb + (size_t)k * 512);
        acc0 = fma2(pack2(p0[k], p0[k]), v2, acc0);
        acc1 = fma2(pack2(p1[k], p1[k]), v2, acc1);
    }
    *(ull*)(g_outh + ((size_t)(n * 256 + q0))     * 512 + w * 64 + 2 * l) = acc0;
    *(ull*)(g_outh + ((size_t)(n * 256 + q0 + 1)) * 512 + w * 64 + 2 * l) = acc1;
}

// ---- kE: out += outh @ Wout^T. 64x128 tile, 4x8/thread, split-K 64/block ----
// epilogue: red.global.add.v4.f32 (vector reductions, sm_90+)
// dyn smem: As[64][68] + Bs[2][64][68] = 13056 floats = 52224 B
__global__ void __launch_bounds__(256)
kE(const float* __restrict__ Wout, float* __restrict__ out) {
    extern __shared__ float sm[];
    float* As = sm;                    // [c][r'] 64x68
    float* Bs = sm + 64 * 68;          // [g][c][j'] 2x64x68
    const int rt = blockIdx.x, jt = blockIdx.y, mt = blockIdx.z;
    const int tid = threadIdx.x;
    const int jid = tid & 15, rid = tid >> 4;

#pragma unroll
    for (int ii = 0; ii < 4; ii++) {
        int flat = ii * 256 + tid;
        int r = flat >> 4, c4 = flat & 15;
        float4 v = *(const float4*)(g_outh +
            (size_t)(rt * 64 + r) * 512 + mt * 64 + c4 * 4);
        float vv[4] = {v.x, v.y, v.z, v.w};
#pragma unroll
        for (int i = 0; i < 4; i++) {
            int c = c4 * 4 + i;
            As[c * 68 + ((((r >> 2) ^ (c & 15)) << 2) | (r & 3))] = vv[i];
        }
    }
#pragma unroll
    for (int ii = 0; ii < 8; ii++) {
        int flat = ii * 256 + tid;
        int r128 = flat >> 4, c4 = flat & 15;
        int g = r128 >> 6, r = r128 & 63;
        float4 v = *(const float4*)(Wout +
            (size_t)(jt * 128 + r128) * 512 + mt * 64 + c4 * 4);
        float vv[4] = {v.x, v.y, v.z, v.w};
#pragma unroll
        for (int i = 0; i < 4; i++) {
            int c = c4 * 4 + i;
            Bs[(g * 64 + c) * 68 + ((((r >> 2) ^ (c & 15)) << 2) | (r & 3))] = vv[i];
        }
    }
    __syncthreads();

    ull acc[4][2][2];
#pragma unroll
    for (int qi = 0; qi < 4; qi++)
#pragma unroll
        for (int g = 0; g < 2; g++) { acc[qi][g][0] = 0; acc[qi][g][1] = 0; }

#pragma unroll 4
    for (int c = 0; c < 64; c++) {
        float4 aq = *(const float4*)&As[c * 68 + ((rid ^ (c & 15)) << 2)];
        ulonglong2 bk0 = *(const ulonglong2*)&Bs[c * 68 + ((jid ^ (c & 15)) << 2)];
        ulonglong2 bk1 = *(const ulonglong2*)&Bs[(64 + c) * 68 + ((jid ^ (c & 15)) << 2)];
        float a4[4] = {aq.x, aq.y, aq.z, aq.w};
#pragma unroll
        for (int qi = 0; qi < 4; qi++) {
            ull a2 = pack2(a4[qi], a4[qi]);
            acc[qi][0][0] = fma2(a2, bk0.x, acc[qi][0][0]);
            acc[qi][0][1] = fma2(a2, bk0.y, acc[qi][0][1]);
            acc[qi][1][0] = fma2(a2, bk1.x, acc[qi][1][0]);
            acc[qi][1][1] = fma2(a2, bk1.y, acc[qi][1][1]);
        }
    }
#pragma unroll
    for (int qi = 0; qi < 4; qi++) {
        int row = rt * 64 + rid * 4 + qi;
#pragma unroll
        for (int g = 0; g < 2; g++) {
            int col = jt * 128 + g * 64 + jid * 4;
            float r0, r1, r2, r3;
            unpk(acc[qi][g][0], r0, r1);
            unpk(acc[qi][g][1], r2, r3);
            float* o = out + (size_t)row * 512 + col;
            asm volatile("red.global.add.v4.f32 [%0], {%1, %2, %3, %4};"
                         :: "l"(o), "f"(r0), "f"(r1), "f"(r2), "f"(r3)
                         : "memory");
        }
    }
}

extern "C" void kernel_launch(void* const* d_in, const int* in_sizes, int n_in,
                              void* d_out, int out_size) {
    const float* values = (const float*)d_in[0];
    const float* keys   = (const float*)d_in[1];
    const float* query  = (const float*)d_in[2];
    const float* pos    = (const float*)d_in[3];
    const float* rel    = (const float*)d_in[4];
    const float* mask   = (const float*)d_in[5];
    const float* Wv   = (const float*)d_in[6];
    const float* Wk   = (const float*)d_in[7];
    const float* Wq   = (const float*)d_in[8];
    const float* Wpq  = (const float*)d_in[9];
    const float* Wpk  = (const float*)d_in[10];
    const float* Wrk  = (const float*)d_in[11];
    const float* Wrq  = (const float*)d_in[12];
    const float* Wout = (const float*)d_in[13];
    const float* bout = (const float*)d_in[14];
    float* out = (float*)d_out;

    static bool attr_done = false;
    if (!attr_done) {
        cudaFuncSetAttribute(kE, cudaFuncAttributeMaxDynamicSharedMemorySize, 52224);
        attr_done = true;
    }

    kA<<<dim3(8, 8, 4), 256>>>(query, keys, pos, values,
                               Wq, Wk, Wpq, Wpk, Wrk, Wrq, Wv);
    kB<<<dim3(16, HH, NB), 256>>>(mask, bout, out);
    kC<<<dim3(LL / 2, NB), 256>>>(rel);
    kE<<<dim3(8, 4, 8), 256, 52224>>>(Wout, out);
}

// round 14
// speedup vs baseline: 1.1895x; 1.0211x over previous
#include <cuda_runtime.h>
#include <cstdint>

#define NB 2
#define LL 256
#define HH 8
#define DD 64
#define EE 512
#define INVS 0.70710678118654752440f

typedef unsigned long long ull;

__device__ __forceinline__ ull fma2(ull a, ull b, ull c) {
    ull d;
    asm("fma.rn.f32x2 %0, %1, %2, %3;" : "=l"(d) : "l"(a), "l"(b), "l"(c));
    return d;
}
__device__ __forceinline__ ull add2(ull a, ull b) {
    ull d;
    asm("add.rn.f32x2 %0, %1, %2;" : "=l"(d) : "l"(a), "l"(b));
    return d;
}
__device__ __forceinline__ ull pack2(float x, float y) {
    ull d;
    asm("mov.b64 %0, {%1, %2};" : "=l"(d) : "r"(__float_as_uint(x)), "r"(__float_as_uint(y)));
    return d;
}
__device__ __forceinline__ float lohi(ull s) {
    unsigned lo, hi;
    asm("mov.b64 {%0, %1}, %2;" : "=r"(lo), "=r"(hi) : "l"(s));
    return __uint_as_float(lo) + __uint_as_float(hi);
}
__device__ __forceinline__ void unpk(ull s, float& a, float& b) {
    unsigned lo, hi;
    asm("mov.b64 {%0, %1}, %2;" : "=r"(lo), "=r"(hi) : "l"(s));
    a = __uint_as_float(lo);
    b = __uint_as_float(hi);
}

// ---- scratch ----
__device__ float g_qm[NB * LL * EE];   // q @ Wq^T * INVS
__device__ float g_k [NB * LL * EE];   // k @ Wk^T
__device__ float g_pq[NB * LL * EE];   // p @ Wpq^T * INVS
__device__ float g_pk[NB * LL * EE];   // p @ Wpk^T
__device__ float g_a [NB * LL * EE];   // qm @ Wrk  (INVS via qm)
__device__ float g_b [NB * LL * EE];   // (k' @ Wrq) * INVS
__device__ float g_vp[NB * LL * EE];   // v @ Wv^T
__device__ float g_base[NB * HH * LL * LL];
__device__ float g_outh[NB * LL * EE];

// ---- kA: per-head chained GEMMs. grid (rowtile 8, head 8, group 4) ----
// z=3 blocks (vp only) additionally init g_base with mask term and out with bias.
__global__ void __launch_bounds__(256)
kA(const float* __restrict__ query, const float* __restrict__ keys,
   const float* __restrict__ pos,   const float* __restrict__ values,
   const float* __restrict__ Wq,  const float* __restrict__ Wk,
   const float* __restrict__ Wpq, const float* __restrict__ Wpk,
   const float* __restrict__ Wrk, const float* __restrict__ Wrq,
   const float* __restrict__ Wv,
   const float* __restrict__ mask, const float* __restrict__ bout,
   float* __restrict__ out) {
    __shared__ float Xs[64][68];
    __shared__ float Ys[64][68];
    __shared__ float W1s[64][64];
    __shared__ float W2s[64][64];
    const int rt = blockIdx.x, h = blockIdx.y, z = blockIdx.z;
    const int tid = threadIdx.x;
    const int cid = tid & 15, rid = tid >> 4;

    const float* src = (z == 0) ? query : (z == 1) ? keys : (z == 2) ? pos : values;
    const float* W1  = (z == 0) ? Wq    : (z == 1) ? Wk   : (z == 2) ? Wpq : Wv;
    const float* W2  = (z == 0) ? Wrk   : (z == 1) ? Wrq  : Wpk;

#pragma unroll
    for (int ii = 0; ii < 4; ii++) {
        int flat = ii * 256 + tid;
        int r = flat >> 4, c4 = flat & 15;
        *(float4*)&Xs[r][c4 * 4] =
            *(const float4*)(src + (size_t)(rt * 64 + r) * 512 + h * 64 + c4 * 4);
    }
#pragma unroll
    for (int ii = 0; ii < 4; ii++) {
        int flat = ii * 256 + tid;
        int i = flat >> 4, m4 = flat & 15;
        float4 wv = *(const float4*)(W1 + (size_t)i * 64 + m4 * 4);
        float w4[4] = {wv.x, wv.y, wv.z, wv.w};
#pragma unroll
        for (int j = 0; j < 4; j++) {
            int m = m4 * 4 + j;
            W1s[m][(((i >> 2) ^ (m & 15)) << 2) + (i & 3)] = w4[j];
        }
    }
    if (z < 2) {
#pragma unroll
        for (int ii = 0; ii < 4; ii++) {
            int flat = ii * 256 + tid;
            int i = flat >> 4, e4 = flat & 15;
            *(float4*)&W2s[i][e4 * 4] = *(const float4*)(W2 + (size_t)i * 64 + e4 * 4);
        }
    } else if (z == 2) {
#pragma unroll
        for (int ii = 0; ii < 4; ii++) {
            int flat = ii * 256 + tid;
            int i = flat >> 4, m4 = flat & 15;
            float4 wv = *(const float4*)(W2 + (size_t)i * 64 + m4 * 4);
            float w4[4] = {wv.x, wv.y, wv.z, wv.w};
#pragma unroll
            for (int j = 0; j < 4; j++) {
                int m = m4 * 4 + j;
                W2s[m][(((i >> 2) ^ (m & 15)) << 2) + (i & 3)] = w4[j];
            }
        }
    }
    __syncthreads();

    ull acc[4][2];
#pragma unroll
    for (int rj = 0; rj < 4; rj++) { acc[rj][0] = 0; acc[rj][1] = 0; }
#pragma unroll 4
    for (int m = 0; m < 64; m++) {
        ulonglong2 wv = *(const ulonglong2*)&W1s[m][(cid ^ (m & 15)) << 2];
#pragma unroll
        for (int rj = 0; rj < 4; rj++) {
            float xa = Xs[rj * 16 + rid][m];
            ull xa2 = pack2(xa, xa);
            acc[rj][0] = fma2(xa2, wv.x, acc[rj][0]);
            acc[rj][1] = fma2(xa2, wv.y, acc[rj][1]);
        }
    }
    float s1 = (z == 0 || z == 2) ? INVS : 1.0f;
    float* out1 = (z == 0) ? g_qm : (z == 1) ? g_k : (z == 2) ? g_pq : g_vp;
    ull s1v = pack2(s1, s1);
#pragma unroll
    for (int rj = 0; rj < 4; rj++) {
        int row = rj * 16 + rid;
        ulonglong2 o;
        o.x = fma2(acc[rj][0], s1v, 0ull);
        o.y = fma2(acc[rj][1], s1v, 0ull);
        *(ulonglong2*)(out1 + (size_t)(rt * 64 + row) * 512 + h * 64 + cid * 4) = o;
        *(ulonglong2*)&Ys[row][cid * 4] = o;
    }
    if (z == 3) {
        // ---- init g_base with mask term; init out with bias ----
        // g_base: 262144 float4 total, 64 blocks -> 4096 float4 each (16 iters x 256).
        // Block lb covers slab quarter: n = lb>>5, within-row float4 col = tid&63.
        int lb = rt * 8 + h;              // 0..63
        int n = lb >> 5;
        float4 m4 = *(const float4*)(mask + n * 256 + (tid & 63) * 4);
        float4 nm;
        nm.x = (1.0f - m4.x) * -1e9f;
        nm.y = (1.0f - m4.y) * -1e9f;
        nm.z = (1.0f - m4.z) * -1e9f;
        nm.w = (1.0f - m4.w) * -1e9f;
        float4* bp = (float4*)g_base;
        size_t f0 = (size_t)lb * 4096 + tid;
#pragma unroll 8
        for (int i = 0; i < 16; i++)
            bp[f0 + (size_t)i * 256] = nm;

        // out: 131072 float4 total, 64 blocks -> 2048 float4 each (8 iters x 256).
        // Row is 128 float4 wide; col = tid&127 matches bias vector.
        float4 bb = *(const float4*)(bout + (tid & 127) * 4);
        float4* op = (float4*)out;
        size_t g0 = (size_t)lb * 2048 + tid;
#pragma unroll
        for (int i = 0; i < 8; i++)
            op[g0 + (size_t)i * 256] = bb;
        return;
    }
    __syncthreads();

    ull acc2[4][2];
#pragma unroll
    for (int rj = 0; rj < 4; rj++) { acc2[rj][0] = 0; acc2[rj][1] = 0; }
    if (z < 2) {
#pragma unroll 4
        for (int i = 0; i < 64; i++) {
            ulonglong2 wv = *(const ulonglong2*)&W2s[i][cid * 4];
#pragma unroll
            for (int rj = 0; rj < 4; rj++) {
                float ya = Ys[rj * 16 + rid][i];
                ull ya2 = pack2(ya, ya);
                acc2[rj][0] = fma2(ya2, wv.x, acc2[rj][0]);
                acc2[rj][1] = fma2(ya2, wv.y, acc2[rj][1]);
            }
        }
    } else {
#pragma unroll 4
        for (int m = 0; m < 64; m++) {
            ulonglong2 wv = *(const ulonglong2*)&W2s[m][(cid ^ (m & 15)) << 2];
#pragma unroll
            for (int rj = 0; rj < 4; rj++) {
                float xa = Xs[rj * 16 + rid][m];
                ull xa2 = pack2(xa, xa);
                acc2[rj][0] = fma2(xa2, wv.x, acc2[rj][0]);
                acc2[rj][1] = fma2(xa2, wv.y, acc2[rj][1]);
            }
        }
    }
    float s2 = (z == 1) ? INVS : 1.0f;
    float* out2 = (z == 0) ? g_a : (z == 1) ? g_b : g_pk;
    ull s2v = pack2(s2, s2);
#pragma unroll
    for (int rj = 0; rj < 4; rj++) {
        int row = rj * 16 + rid;
        ulonglong2 o;
        o.x = fma2(acc2[rj][0], s2v, 0ull);
        o.y = fma2(acc2[rj][1], s2v, 0ull);
        *(ulonglong2*)(out2 + (size_t)(rt * 64 + row) * 512 + h * 64 + cid * 4) = o;
    }
}

// ---- kB: g_base += (single source pass). grid (16, 8, 4): z = n*2 + s ----
__global__ void __launch_bounds__(256)
kB() {
    __shared__ float As[64][68];
    __shared__ float Bs[64][68];
    const int qt = blockIdx.x >> 2, kt = blockIdx.x & 3;
    const int h = blockIdx.y;
    const int n = blockIdx.z >> 1, s = blockIdx.z & 1;
    const int tid = threadIdx.x;
    const int jid = tid & 15, rid = tid >> 4;

    const float* Aop = s ? g_pq : g_qm;
    const float* Bop = s ? g_pk : g_k;
#pragma unroll
    for (int ii = 0; ii < 8; ii++) {
        int flat = ii * 256 + tid;
        int arr = flat >> 10;
        int r = (flat >> 4) & 63;
        int c4 = flat & 15;
        const float* src = arr
            ? Bop + (size_t)(n * 256 + kt * 64 + r) * 512
            : Aop + (size_t)(n * 256 + qt * 64 + r) * 512;
        float4 v = *(const float4*)(src + h * 64 + c4 * 4);
        float* dst = arr ? &Bs[0][0] : &As[0][0];
        float vv[4] = {v.x, v.y, v.z, v.w};
#pragma unroll
        for (int i = 0; i < 4; i++) {
            int c = c4 * 4 + i;
            dst[c * 68 + ((((r >> 2) ^ (c & 15)) << 2) | (r & 3))] = vv[i];
        }
    }
    __syncthreads();

    ull acc[4][2];
#pragma unroll
    for (int qi = 0; qi < 4; qi++) { acc[qi][0] = 0; acc[qi][1] = 0; }
#pragma unroll 4
    for (int c = 0; c < 64; c++) {
        float4 aq = *(const float4*)&As[c][(rid ^ (c & 15)) << 2];
        ulonglong2 bk = *(const ulonglong2*)&Bs[c][(jid ^ (c & 15)) << 2];
        float a4[4] = {aq.x, aq.y, aq.z, aq.w};
#pragma unroll
        for (int qi = 0; qi < 4; qi++) {
            ull a2 = pack2(a4[qi], a4[qi]);
            acc[qi][0] = fma2(a2, bk.x, acc[qi][0]);
            acc[qi][1] = fma2(a2, bk.y, acc[qi][1]);
        }
    }
#pragma unroll
    for (int qi = 0; qi < 4; qi++) {
        int q = qt * 64 + rid * 4 + qi;
        float r0, r1, r2, r3;
        unpk(acc[qi][0], r0, r1);
        unpk(acc[qi][1], r2, r3);
        float* o = &g_base[((size_t)((n * 8 + h) * 256 + q)) * 256 + kt * 64 + jid * 4];
        asm volatile("red.global.add.v4.f32 [%0], {%1, %2, %3, %4};"
                     :: "l"(o), "f"(r0), "f"(r1), "f"(r2), "f"(r3)
                     : "memory");
    }
}

// ---- kC: coalesced rel stream (evict-first) + exchange reduce + softmax + attn@v ----
__global__ void __launch_bounds__(256, 2)
kC(const float* __restrict__ rel) {
    __shared__ float eng[2 * 8 * 260];
    const int n = blockIdx.y;
    const int q0 = blockIdx.x * 2;
    const int tid = threadIdx.x;
    const int w = tid >> 5, l = tid & 31;
    const bool b3 = (l & 8) != 0;
    const bool b2v = (l & 4) != 0;
    const int head = (l >> 4) + (b3 ? 4 : 0) + (b2v ? 2 : 0);

#pragma unroll
    for (int ii = 0; ii < 4; ii++) {
        int flat = ii * 256 + tid;
        int qi = flat >> 9, h = (flat >> 6) & 7, k4 = flat & 63;
        float4 v = *(const float4*)(g_base +
            ((size_t)((n * 8 + h) * 256 + q0 + qi)) * 256 + k4 * 4);
        float* e = &eng[(qi * 8 + h) * 260 + k4 * 4];
        e[0] = v.x; e[1] = v.y; e[2] = v.z; e[3] = v.w;
    }
    ulonglong2 areg[2][4];
#pragma unroll
    for (int q = 0; q < 2; q++)
#pragma unroll
        for (int u = 0; u < 4; u++)
            areg[q][u] = *(const ulonglong2*)(g_a +
                (size_t)(n * 256 + q0 + q) * 512 + u * 128 + l * 4);
    __syncthreads();

    const float* relb = rel + ((size_t)(n * 256 + q0)) * 256 * 512 + l * 4;
    const float* bbas = g_b + (size_t)n * 256 * 512 + l * 4;

    for (int t = 0; t < 32; t++) {
        const int k = t * 8 + w;
        const float* brow = bbas + (size_t)k * 512;
        const float* r0p  = relb + (size_t)k * 512;
        const float* r1p  = r0p + 256 * 512;
        ulonglong2 B[4], R0[4], R1[4];
#pragma unroll
        for (int u = 0; u < 4; u++) B[u]  = *(const ulonglong2*)(brow + u * 128);
#pragma unroll
        for (int u = 0; u < 4; u++) R0[u] = __ldcs((const ulonglong2*)(r0p + u * 128));
#pragma unroll
        for (int u = 0; u < 4; u++) R1[u] = __ldcs((const ulonglong2*)(r1p + u * 128));

        float s0[4], s1[4];
#pragma unroll
        for (int u = 0; u < 4; u++) {
            ull c0 = add2(areg[0][u].x, B[u].x);
            ull c1 = add2(areg[0][u].y, B[u].y);
            ull P  = fma2(R0[u].x, c0, 0ull);
            P      = fma2(R0[u].y, c1, P);
            s0[u] = lohi(P);
            ull d0 = add2(areg[1][u].x, B[u].x);
            ull d1 = add2(areg[1][u].y, B[u].y);
            ull Q  = fma2(R1[u].x, d0, 0ull);
            Q      = fma2(R1[u].y, d1, Q);
            s1[u] = lohi(Q);
        }
        float f, g;
        {
            float t0 = __shfl_xor_sync(0xffffffffu, s0[0], 8);
            float t1 = __shfl_xor_sync(0xffffffffu, s0[1], 8);
            float t2 = __shfl_xor_sync(0xffffffffu, s0[2], 8);
            float t3 = __shfl_xor_sync(0xffffffffu, s0[3], 8);
            float e0 = b3 ? (s0[2] + t2) : (s0[0] + t0);
            float e1 = b3 ? (s0[3] + t3) : (s0[1] + t1);
            float u0 = __shfl_xor_sync(0xffffffffu, e0, 4);
            float u1 = __shfl_xor_sync(0xffffffffu, e1, 4);
            f = b2v ? (e1 + u1) : (e0 + u0);
            f += __shfl_xor_sync(0xffffffffu, f, 1);
            f += __shfl_xor_sync(0xffffffffu, f, 2);
        }
        {
            float t0 = __shfl_xor_sync(0xffffffffu, s1[0], 8);
            float t1 = __shfl_xor_sync(0xffffffffu, s1[1], 8);
            float t2 = __shfl_xor_sync(0xffffffffu, s1[2], 8);
            float t3 = __shfl_xor_sync(0xffffffffu, s1[3], 8);
            float e0 = b3 ? (s1[2] + t2) : (s1[0] + t0);
            float e1 = b3 ? (s1[3] + t3) : (s1[1] + t1);
            float u0 = __shfl_xor_sync(0xffffffffu, e0, 4);
            float u1 = __shfl_xor_sync(0xffffffffu, e1, 4);
            g = b2v ? (e1 + u1) : (e0 + u0);
            g += __shfl_xor_sync(0xffffffffu, g, 1);
            g += __shfl_xor_sync(0xffffffffu, g, 2);
        }
        if ((l & 3) == 0) {
            eng[(0 * 8 + head) * 260 + k] += f;
            eng[(1 * 8 + head) * 260 + k] += g;
        }
    }
    __syncthreads();

#pragma unroll
    for (int qi = 0; qi < 2; qi++) {
        float v[8];
        float m = -1e30f;
#pragma unroll
        for (int j = 0; j < 8; j++) {
            v[j] = eng[(qi * 8 + w) * 260 + l + 32 * j];
            m = fmaxf(m, v[j]);
        }
#pragma unroll
        for (int off = 16; off; off >>= 1)
            m = fmaxf(m, __shfl_xor_sync(0xffffffffu, m, off));
        float s = 0.f;
#pragma unroll
        for (int j = 0; j < 8; j++) {
            v[j] = __expf(v[j] - m);
            s += v[j];
        }
#pragma unroll
        for (int off = 16; off; off >>= 1)
            s += __shfl_xor_sync(0xffffffffu, s, off);
        float inv = 1.0f / s;
#pragma unroll
        for (int j = 0; j < 8; j++)
            eng[(qi * 8 + w) * 260 + l + 32 * j] = v[j] * inv;
    }
    __syncwarp();

    ull acc0 = 0, acc1 = 0;
    const float* vpb = g_vp + (size_t)n * 256 * 512 + w * 64 + 2 * l;
    const float* p0 = &eng[(0 * 8 + w) * 260];
    const float* p1 = &eng[(1 * 8 + w) * 260];
#pragma unroll 8
    for (int k = 0; k < 256; k++) {
        ull v2 = *(const ull*)(vpb + (size_t)k * 512);
        acc0 = fma2(pack2(p0[k], p0[k]), v2, acc0);
        acc1 = fma2(pack2(p1[k], p1[k]), v2, acc1);
    }
    *(ull*)(g_outh + ((size_t)(n * 256 + q0))     * 512 + w * 64 + 2 * l) = acc0;
    *(ull*)(g_outh + ((size_t)(n * 256 + q0 + 1)) * 512 + w * 64 + 2 * l) = acc1;
}

// ---- kE: out += outh @ Wout^T. 64x128 tile, 4x8/thread, split-K 64/block ----
// dyn smem: As[64][68] + Bs[2][64][68] = 13056 floats = 52224 B
__global__ void __launch_bounds__(256)
kE(const float* __restrict__ Wout, float* __restrict__ out) {
    extern __shared__ float sm[];
    float* As = sm;                    // [c][r'] 64x68
    float* Bs = sm + 64 * 68;          // [g][c][j'] 2x64x68
    const int rt = blockIdx.x, jt = blockIdx.y, mt = blockIdx.z;
    const int tid = threadIdx.x;
    const int jid = tid & 15, rid = tid >> 4;

#pragma unroll
    for (int ii = 0; ii < 4; ii++) {
        int flat = ii * 256 + tid;
        int r = flat >> 4, c4 = flat & 15;
        float4 v = *(const float4*)(g_outh +
            (size_t)(rt * 64 + r) * 512 + mt * 64 + c4 * 4);
        float vv[4] = {v.x, v.y, v.z, v.w};
#pragma unroll
        for (int i = 0; i < 4; i++) {
            int c = c4 * 4 + i;
            As[c * 68 + ((((r >> 2) ^ (c & 15)) << 2) | (r & 3))] = vv[i];
        }
    }
#pragma unroll
    for (int ii = 0; ii < 8; ii++) {
        int flat = ii * 256 + tid;
        int r128 = flat >> 4, c4 = flat & 15;
        int g = r128 >> 6, r = r128 & 63;
        float4 v = *(const float4*)(Wout +
            (size_t)(jt * 128 + r128) * 512 + mt * 64 + c4 * 4);
        float vv[4] = {v.x, v.y, v.z, v.w};
#pragma unroll
        for (int i = 0; i < 4; i++) {
            int c = c4 * 4 + i;
            Bs[(g * 64 + c) * 68 + ((((r >> 2) ^ (c & 15)) << 2) | (r & 3))] = vv[i];
        }
    }
    __syncthreads();

    ull acc[4][2][2];
#pragma unroll
    for (int qi = 0; qi < 4; qi++)
#pragma unroll
        for (int g = 0; g < 2; g++) { acc[qi][g][0] = 0; acc[qi][g][1] = 0; }

#pragma unroll 4
    for (int c = 0; c < 64; c++) {
        float4 aq = *(const float4*)&As[c * 68 + ((rid ^ (c & 15)) << 2)];
        ulonglong2 bk0 = *(const ulonglong2*)&Bs[c * 68 + ((jid ^ (c & 15)) << 2)];
        ulonglong2 bk1 = *(const ulonglong2*)&Bs[(64 + c) * 68 + ((jid ^ (c & 15)) << 2)];
        float a4[4] = {aq.x, aq.y, aq.z, aq.w};
#pragma unroll
        for (int qi = 0; qi < 4; qi++) {
            ull a2 = pack2(a4[qi], a4[qi]);
            acc[qi][0][0] = fma2(a2, bk0.x, acc[qi][0][0]);
            acc[qi][0][1] = fma2(a2, bk0.y, acc[qi][0][1]);
            acc[qi][1][0] = fma2(a2, bk1.x, acc[qi][1][0]);
            acc[qi][1][1] = fma2(a2, bk1.y, acc[qi][1][1]);
        }
    }
#pragma unroll
    for (int qi = 0; qi < 4; qi++) {
        int row = rt * 64 + rid * 4 + qi;
#pragma unroll
        for (int g = 0; g < 2; g++) {
            int col = jt * 128 + g * 64 + jid * 4;
            float r0, r1, r2, r3;
            unpk(acc[qi][g][0], r0, r1);
            unpk(acc[qi][g][1], r2, r3);
            float* o = out + (size_t)row * 512 + col;
            asm volatile("red.global.add.v4.f32 [%0], {%1, %2, %3, %4};"
                         :: "l"(o), "f"(r0), "f"(r1), "f"(r2), "f"(r3)
                         : "memory");
        }
    }
}

extern "C" void kernel_launch(void* const* d_in, const int* in_sizes, int n_in,
                              void* d_out, int out_size) {
    const float* values = (const float*)d_in[0];
    const float* keys   = (const float*)d_in[1];
    const float* query  = (const float*)d_in[2];
    const float* pos    = (const float*)d_in[3];
    const float* rel    = (const float*)d_in[4];
    const float* mask   = (const float*)d_in[5];
    const float* Wv   = (const float*)d_in[6];
    const float* Wk   = (const float*)d_in[7];
    const float* Wq   = (const float*)d_in[8];
    const float* Wpq  = (const float*)d_in[9];
    const float* Wpk  = (const float*)d_in[10];
    const float* Wrk  = (const float*)d_in[11];
    const float* Wrq  = (const float*)d_in[12];
    const float* Wout = (const float*)d_in[13];
    const float* bout = (const float*)d_in[14];
    float* out = (float*)d_out;

    static bool attr_done = false;
    if (!attr_done) {
        cudaFuncSetAttribute(kE, cudaFuncAttributeMaxDynamicSharedMemorySize, 52224);
        attr_done = true;
    }

    kA<<<dim3(8, 8, 4), 256>>>(query, keys, pos, values,
                               Wq, Wk, Wpq, Wpk, Wrk, Wrq, Wv,
                               mask, bout, out);
    kB<<<dim3(16, HH, 4), 256>>>();
    kC<<<dim3(LL / 2, NB), 256>>>(rel);
    kE<<<dim3(8, 4, 8), 256, 52224>>>(Wout, out);
}

// round 15
// speedup vs baseline: 1.2256x; 1.0304x over previous
#include <cuda_runtime.h>
#include <cstdint>

#define NB 2
#define LL 256
#define HH 8
#define DD 64
#define EE 512
#define INVS 0.70710678118654752440f

typedef unsigned long long ull;

__device__ __forceinline__ ull fma2(ull a, ull b, ull c) {
    ull d;
    asm("fma.rn.f32x2 %0, %1, %2, %3;" : "=l"(d) : "l"(a), "l"(b), "l"(c));
    return d;
}
__device__ __forceinline__ ull add2(ull a, ull b) {
    ull d;
    asm("add.rn.f32x2 %0, %1, %2;" : "=l"(d) : "l"(a), "l"(b));
    return d;
}
__device__ __forceinline__ ull pack2(float x, float y) {
    ull d;
    asm("mov.b64 %0, {%1, %2};" : "=l"(d) : "r"(__float_as_uint(x)), "r"(__float_as_uint(y)));
    return d;
}
__device__ __forceinline__ float lohi(ull s) {
    unsigned lo, hi;
    asm("mov.b64 {%0, %1}, %2;" : "=r"(lo), "=r"(hi) : "l"(s));
    return __uint_as_float(lo) + __uint_as_float(hi);
}
__device__ __forceinline__ void unpk(ull s, float& a, float& b) {
    unsigned lo, hi;
    asm("mov.b64 {%0, %1}, %2;" : "=r"(lo), "=r"(hi) : "l"(s));
    a = __uint_as_float(lo);
    b = __uint_as_float(hi);
}

// ---- scratch ----
__device__ float g_qm[NB * LL * EE];   // q @ Wq^T * INVS
__device__ float g_k [NB * LL * EE];   // k @ Wk^T
__device__ float g_pq[NB * LL * EE];   // p @ Wpq^T * INVS
__device__ float g_pk[NB * LL * EE];   // p @ Wpk^T
__device__ float g_a [NB * LL * EE];   // qm @ Wrk  (INVS via qm)
__device__ float g_b [NB * LL * EE];   // (k' @ Wrq) * INVS
__device__ float g_vp[NB * LL * EE];   // v @ Wv^T
__device__ float g_base[NB * HH * LL * LL];
__device__ float g_outh[NB * LL * EE];

// ---- kA: per-head chained GEMMs. grid (rowtile 8, head 8, group 4) ----
// z=3 blocks (vp only) additionally init g_base with mask term and out with bias.
__global__ void __launch_bounds__(256)
kA(const float* __restrict__ query, const float* __restrict__ keys,
   const float* __restrict__ pos,   const float* __restrict__ values,
   const float* __restrict__ Wq,  const float* __restrict__ Wk,
   const float* __restrict__ Wpq, const float* __restrict__ Wpk,
   const float* __restrict__ Wrk, const float* __restrict__ Wrq,
   const float* __restrict__ Wv,
   const float* __restrict__ mask, const float* __restrict__ bout,
   float* __restrict__ out) {
    __shared__ float Xs[64][68];
    __shared__ float Ys[64][68];
    __shared__ float W1s[64][64];
    __shared__ float W2s[64][64];
    const int rt = blockIdx.x, h = blockIdx.y, z = blockIdx.z;
    const int tid = threadIdx.x;
    const int cid = tid & 15, rid = tid >> 4;

    const float* src = (z == 0) ? query : (z == 1) ? keys : (z == 2) ? pos : values;
    const float* W1  = (z == 0) ? Wq    : (z == 1) ? Wk   : (z == 2) ? Wpq : Wv;
    const float* W2  = (z == 0) ? Wrk   : (z == 1) ? Wrq  : Wpk;

#pragma unroll
    for (int ii = 0; ii < 4; ii++) {
        int flat = ii * 256 + tid;
        int r = flat >> 4, c4 = flat & 15;
        *(float4*)&Xs[r][c4 * 4] =
            *(const float4*)(src + (size_t)(rt * 64 + r) * 512 + h * 64 + c4 * 4);
    }
#pragma unroll
    for (int ii = 0; ii < 4; ii++) {
        int flat = ii * 256 + tid;
        int i = flat >> 4, m4 = flat & 15;
        float4 wv = *(const float4*)(W1 + (size_t)i * 64 + m4 * 4);
        float w4[4] = {wv.x, wv.y, wv.z, wv.w};
#pragma unroll
        for (int j = 0; j < 4; j++) {
            int m = m4 * 4 + j;
            W1s[m][(((i >> 2) ^ (m & 15)) << 2) + (i & 3)] = w4[j];
        }
    }
    if (z < 2) {
#pragma unroll
        for (int ii = 0; ii < 4; ii++) {
            int flat = ii * 256 + tid;
            int i = flat >> 4, e4 = flat & 15;
            *(float4*)&W2s[i][e4 * 4] = *(const float4*)(W2 + (size_t)i * 64 + e4 * 4);
        }
    } else if (z == 2) {
#pragma unroll
        for (int ii = 0; ii < 4; ii++) {
            int flat = ii * 256 + tid;
            int i = flat >> 4, m4 = flat & 15;
            float4 wv = *(const float4*)(W2 + (size_t)i * 64 + m4 * 4);
            float w4[4] = {wv.x, wv.y, wv.z, wv.w};
#pragma unroll
            for (int j = 0; j < 4; j++) {
                int m = m4 * 4 + j;
                W2s[m][(((i >> 2) ^ (m & 15)) << 2) + (i & 3)] = w4[j];
            }
        }
    }
    __syncthreads();

    ull acc[4][2];
#pragma unroll
    for (int rj = 0; rj < 4; rj++) { acc[rj][0] = 0; acc[rj][1] = 0; }
#pragma unroll 4
    for (int m = 0; m < 64; m++) {
        ulonglong2 wv = *(const ulonglong2*)&W1s[m][(cid ^ (m & 15)) << 2];
#pragma unroll
        for (int rj = 0; rj < 4; rj++) {
            float xa = Xs[rj * 16 + rid][m];
            ull xa2 = pack2(xa, xa);
            acc[rj][0] = fma2(xa2, wv.x, acc[rj][0]);
            acc[rj][1] = fma2(xa2, wv.y, acc[rj][1]);
        }
    }
    float s1 = (z == 0 || z == 2) ? INVS : 1.0f;
    float* out1 = (z == 0) ? g_qm : (z == 1) ? g_k : (z == 2) ? g_pq : g_vp;
    ull s1v = pack2(s1, s1);
#pragma unroll
    for (int rj = 0; rj < 4; rj++) {
        int row = rj * 16 + rid;
        ulonglong2 o;
        o.x = fma2(acc[rj][0], s1v, 0ull);
        o.y = fma2(acc[rj][1], s1v, 0ull);
        *(ulonglong2*)(out1 + (size_t)(rt * 64 + row) * 512 + h * 64 + cid * 4) = o;
        *(ulonglong2*)&Ys[row][cid * 4] = o;
    }
    if (z == 3) {
        // ---- init g_base with mask term; init out with bias ----
        int lb = rt * 8 + h;              // 0..63
        int n = lb >> 5;
        float4 m4 = *(const float4*)(mask + n * 256 + (tid & 63) * 4);
        float4 nm;
        nm.x = (1.0f - m4.x) * -1e9f;
        nm.y = (1.0f - m4.y) * -1e9f;
        nm.z = (1.0f - m4.z) * -1e9f;
        nm.w = (1.0f - m4.w) * -1e9f;
        float4* bp = (float4*)g_base;
        size_t f0 = (size_t)lb * 4096 + tid;
#pragma unroll 8
        for (int i = 0; i < 16; i++)
            bp[f0 + (size_t)i * 256] = nm;

        float4 bb = *(const float4*)(bout + (tid & 127) * 4);
        float4* op = (float4*)out;
        size_t g0 = (size_t)lb * 2048 + tid;
#pragma unroll
        for (int i = 0; i < 8; i++)
            op[g0 + (size_t)i * 256] = bb;
        return;
    }
    __syncthreads();

    ull acc2[4][2];
#pragma unroll
    for (int rj = 0; rj < 4; rj++) { acc2[rj][0] = 0; acc2[rj][1] = 0; }
    if (z < 2) {
#pragma unroll 4
        for (int i = 0; i < 64; i++) {
            ulonglong2 wv = *(const ulonglong2*)&W2s[i][cid * 4];
#pragma unroll
            for (int rj = 0; rj < 4; rj++) {
                float ya = Ys[rj * 16 + rid][i];
                ull ya2 = pack2(ya, ya);
                acc2[rj][0] = fma2(ya2, wv.x, acc2[rj][0]);
                acc2[rj][1] = fma2(ya2, wv.y, acc2[rj][1]);
            }
        }
    } else {
#pragma unroll 4
        for (int m = 0; m < 64; m++) {
            ulonglong2 wv = *(const ulonglong2*)&W2s[m][(cid ^ (m & 15)) << 2];
#pragma unroll
            for (int rj = 0; rj < 4; rj++) {
                float xa = Xs[rj * 16 + rid][m];
                ull xa2 = pack2(xa, xa);
                acc2[rj][0] = fma2(xa2, wv.x, acc2[rj][0]);
                acc2[rj][1] = fma2(xa2, wv.y, acc2[rj][1]);
            }
        }
    }
    float s2 = (z == 1) ? INVS : 1.0f;
    float* out2 = (z == 0) ? g_a : (z == 1) ? g_b : g_pk;
    ull s2v = pack2(s2, s2);
#pragma unroll
    for (int rj = 0; rj < 4; rj++) {
        int row = rj * 16 + rid;
        ulonglong2 o;
        o.x = fma2(acc2[rj][0], s2v, 0ull);
        o.y = fma2(acc2[rj][1], s2v, 0ull);
        *(ulonglong2*)(out2 + (size_t)(rt * 64 + row) * 512 + h * 64 + cid * 4) = o;
    }
}

// ---- kB: g_base += (single source pass). grid (16, 8, 4): z = n*2 + s ----
__global__ void __launch_bounds__(256)
kB() {
    __shared__ float As[64][68];
    __shared__ float Bs[64][68];
    const int qt = blockIdx.x >> 2, kt = blockIdx.x & 3;
    const int h = blockIdx.y;
    const int n = blockIdx.z >> 1, s = blockIdx.z & 1;
    const int tid = threadIdx.x;
    const int jid = tid & 15, rid = tid >> 4;

    const float* Aop = s ? g_pq : g_qm;
    const float* Bop = s ? g_pk : g_k;
#pragma unroll
    for (int ii = 0; ii < 8; ii++) {
        int flat = ii * 256 + tid;
        int arr = flat >> 10;
        int r = (flat >> 4) & 63;
        int c4 = flat & 15;
        const float* src = arr
            ? Bop + (size_t)(n * 256 + kt * 64 + r) * 512
            : Aop + (size_t)(n * 256 + qt * 64 + r) * 512;
        float4 v = *(const float4*)(src + h * 64 + c4 * 4);
        float* dst = arr ? &Bs[0][0] : &As[0][0];
        float vv[4] = {v.x, v.y, v.z, v.w};
#pragma unroll
        for (int i = 0; i < 4; i++) {
            int c = c4 * 4 + i;
            dst[c * 68 + ((((r >> 2) ^ (c & 15)) << 2) | (r & 3))] = vv[i];
        }
    }
    __syncthreads();

    ull acc[4][2];
#pragma unroll
    for (int qi = 0; qi < 4; qi++) { acc[qi][0] = 0; acc[qi][1] = 0; }
#pragma unroll 4
    for (int c = 0; c < 64; c++) {
        float4 aq = *(const float4*)&As[c][(rid ^ (c & 15)) << 2];
        ulonglong2 bk = *(const ulonglong2*)&Bs[c][(jid ^ (c & 15)) << 2];
        float a4[4] = {aq.x, aq.y, aq.z, aq.w};
#pragma unroll
        for (int qi = 0; qi < 4; qi++) {
            ull a2 = pack2(a4[qi], a4[qi]);
            acc[qi][0] = fma2(a2, bk.x, acc[qi][0]);
            acc[qi][1] = fma2(a2, bk.y, acc[qi][1]);
        }
    }
#pragma unroll
    for (int qi = 0; qi < 4; qi++) {
        int q = qt * 64 + rid * 4 + qi;
        float r0, r1, r2, r3;
        unpk(acc[qi][0], r0, r1);
        unpk(acc[qi][1], r2, r3);
        float* o = &g_base[((size_t)((n * 8 + h) * 256 + q)) * 256 + kt * 64 + jid * 4];
        asm volatile("red.global.add.v4.f32 [%0], {%1, %2, %3, %4};"
                     :: "l"(o), "f"(r0), "f"(r1), "f"(r2), "f"(r3)
                     : "memory");
    }
}

// ---- kC: coalesced rel stream (evict-first) + exchange reduce + softmax + attn@v ----
__global__ void __launch_bounds__(256, 2)
kC(const float* __restrict__ rel) {
    __shared__ float eng[2 * 8 * 260];
    const int n = blockIdx.y;
    const int q0 = blockIdx.x * 2;
    const int tid = threadIdx.x;
    const int w = tid >> 5, l = tid & 31;
    const bool b3 = (l & 8) != 0;
    const bool b2v = (l & 4) != 0;
    const int head = (l >> 4) + (b3 ? 4 : 0) + (b2v ? 2 : 0);

#pragma unroll
    for (int ii = 0; ii < 4; ii++) {
        int flat = ii * 256 + tid;
        int qi = flat >> 9, h = (flat >> 6) & 7, k4 = flat & 63;
        float4 v = *(const float4*)(g_base +
            ((size_t)((n * 8 + h) * 256 + q0 + qi)) * 256 + k4 * 4);
        float* e = &eng[(qi * 8 + h) * 260 + k4 * 4];
        e[0] = v.x; e[1] = v.y; e[2] = v.z; e[3] = v.w;
    }
    ulonglong2 areg[2][4];
#pragma unroll
    for (int q = 0; q < 2; q++)
#pragma unroll
        for (int u = 0; u < 4; u++)
            areg[q][u] = *(const ulonglong2*)(g_a +
                (size_t)(n * 256 + q0 + q) * 512 + u * 128 + l * 4);
    __syncthreads();

    const float* relb = rel + ((size_t)(n * 256 + q0)) * 256 * 512 + l * 4;
    const float* bbas = g_b + (size_t)n * 256 * 512 + l * 4;

    for (int t = 0; t < 32; t++) {
        const int k = t * 8 + w;
        const float* brow = bbas + (size_t)k * 512;
        const float* r0p  = relb + (size_t)k * 512;
        const float* r1p  = r0p + 256 * 512;
        ulonglong2 B[4], R0[4], R1[4];
#pragma unroll
        for (int u = 0; u < 4; u++) B[u]  = *(const ulonglong2*)(brow + u * 128);
#pragma unroll
        for (int u = 0; u < 4; u++) R0[u] = __ldcs((const ulonglong2*)(r0p + u * 128));
#pragma unroll
        for (int u = 0; u < 4; u++) R1[u] = __ldcs((const ulonglong2*)(r1p + u * 128));

        float s0[4], s1[4];
#pragma unroll
        for (int u = 0; u < 4; u++) {
            ull c0 = add2(areg[0][u].x, B[u].x);
            ull c1 = add2(areg[0][u].y, B[u].y);
            ull P  = fma2(R0[u].x, c0, 0ull);
            P      = fma2(R0[u].y, c1, P);
            s0[u] = lohi(P);
            ull d0 = add2(areg[1][u].x, B[u].x);
            ull d1 = add2(areg[1][u].y, B[u].y);
            ull Q  = fma2(R1[u].x, d0, 0ull);
            Q      = fma2(R1[u].y, d1, Q);
            s1[u] = lohi(Q);
        }
        float f, g;
        {
            float t0 = __shfl_xor_sync(0xffffffffu, s0[0], 8);
            float t1 = __shfl_xor_sync(0xffffffffu, s0[1], 8);
            float t2 = __shfl_xor_sync(0xffffffffu, s0[2], 8);
            float t3 = __shfl_xor_sync(0xffffffffu, s0[3], 8);
            float e0 = b3 ? (s0[2] + t2) : (s0[0] + t0);
            float e1 = b3 ? (s0[3] + t3) : (s0[1] + t1);
            float u0 = __shfl_xor_sync(0xffffffffu, e0, 4);
            float u1 = __shfl_xor_sync(0xffffffffu, e1, 4);
            f = b2v ? (e1 + u1) : (e0 + u0);
            f += __shfl_xor_sync(0xffffffffu, f, 1);
            f += __shfl_xor_sync(0xffffffffu, f, 2);
        }
        {
            float t0 = __shfl_xor_sync(0xffffffffu, s1[0], 8);
            float t1 = __shfl_xor_sync(0xffffffffu, s1[1], 8);
            float t2 = __shfl_xor_sync(0xffffffffu, s1[2], 8);
            float t3 = __shfl_xor_sync(0xffffffffu, s1[3], 8);
            float e0 = b3 ? (s1[2] + t2) : (s1[0] + t0);
            float e1 = b3 ? (s1[3] + t3) : (s1[1] + t1);
            float u0 = __shfl_xor_sync(0xffffffffu, e0, 4);
            float u1 = __shfl_xor_sync(0xffffffffu, e1, 4);
            g = b2v ? (e1 + u1) : (e0 + u0);
            g += __shfl_xor_sync(0xffffffffu, g, 1);
            g += __shfl_xor_sync(0xffffffffu, g, 2);
        }
        if ((l & 3) == 0) {
            eng[(0 * 8 + head) * 260 + k] += f;
            eng[(1 * 8 + head) * 260 + k] += g;
        }
    }
    __syncthreads();

#pragma unroll
    for (int qi = 0; qi < 2; qi++) {
        float v[8];
        float m = -1e30f;
#pragma unroll
        for (int j = 0; j < 8; j++) {
            v[j] = eng[(qi * 8 + w) * 260 + l + 32 * j];
            m = fmaxf(m, v[j]);
        }
#pragma unroll
        for (int off = 16; off; off >>= 1)
            m = fmaxf(m, __shfl_xor_sync(0xffffffffu, m, off));
        float s = 0.f;
#pragma unroll
        for (int j = 0; j < 8; j++) {
            v[j] = __expf(v[j] - m);
            s += v[j];
        }
#pragma unroll
        for (int off = 16; off; off >>= 1)
            s += __shfl_xor_sync(0xffffffffu, s, off);
        float inv = 1.0f / s;
#pragma unroll
        for (int j = 0; j < 8; j++)
            eng[(qi * 8 + w) * 260 + l + 32 * j] = v[j] * inv;
    }
    __syncwarp();

    ull acc0 = 0, acc1 = 0;
    const float* vpb = g_vp + (size_t)n * 256 * 512 + w * 64 + 2 * l;
    const float* p0 = &eng[(0 * 8 + w) * 260];
    const float* p1 = &eng[(1 * 8 + w) * 260];
#pragma unroll 8
    for (int k = 0; k < 256; k++) {
        ull v2 = *(const ull*)(vpb + (size_t)k * 512);
        acc0 = fma2(pack2(p0[k], p0[k]), v2, acc0);
        acc1 = fma2(pack2(p1[k], p1[k]), v2, acc1);
    }
    *(ull*)(g_outh + ((size_t)(n * 256 + q0))     * 512 + w * 64 + 2 * l) = acc0;
    *(ull*)(g_outh + ((size_t)(n * 256 + q0 + 1)) * 512 + w * 64 + 2 * l) = acc1;
}

// ---- kE: out += outh @ Wout^T. 64x128 tile, 4x8/thread, split-K 32/block ----
// grid (8 rt, 4 jt, 16 mt) = 512 blocks; static smem 26 KB -> ~3.5 CTAs/SM
__global__ void __launch_bounds__(256)
kE(const float* __restrict__ Wout, float* __restrict__ out) {
    __shared__ float As[32 * 68];        // [c][r']
    __shared__ float Bs[2 * 32 * 68];    // [g][c][j']
    const int rt = blockIdx.x, jt = blockIdx.y, mt = blockIdx.z;
    const int tid = threadIdx.x;
    const int jid = tid & 15, rid = tid >> 4;

    // stage A (outh rows rt*64.., k-cols mt*32..): transposed+swizzled
#pragma unroll
    for (int ii = 0; ii < 2; ii++) {
        int flat = ii * 256 + tid;           // 512 float4
        int r = flat >> 3, c4 = flat & 7;
        float4 v = *(const float4*)(g_outh +
            (size_t)(rt * 64 + r) * 512 + mt * 32 + c4 * 4);
        float vv[4] = {v.x, v.y, v.z, v.w};
#pragma unroll
        for (int i = 0; i < 4; i++) {
            int c = c4 * 4 + i;
            As[c * 68 + ((((r >> 2) ^ (c & 15)) << 2) | (r & 3))] = vv[i];
        }
    }
    // stage B (Wout rows jt*128..+128, k-cols mt*32..): transposed+swizzled, 2 groups
#pragma unroll
    for (int ii = 0; ii < 4; ii++) {
        int flat = ii * 256 + tid;           // 1024 float4
        int r128 = flat >> 3, c4 = flat & 7;
        int g = r128 >> 6, r = r128 & 63;
        float4 v = *(const float4*)(Wout +
            (size_t)(jt * 128 + r128) * 512 + mt * 32 + c4 * 4);
        float vv[4] = {v.x, v.y, v.z, v.w};
#pragma unroll
        for (int i = 0; i < 4; i++) {
            int c = c4 * 4 + i;
            Bs[(g * 32 + c) * 68 + ((((r >> 2) ^ (c & 15)) << 2) | (r & 3))] = vv[i];
        }
    }
    __syncthreads();

    ull acc[4][2][2];
#pragma unroll
    for (int qi = 0; qi < 4; qi++)
#pragma unroll
        for (int g = 0; g < 2; g++) { acc[qi][g][0] = 0; acc[qi][g][1] = 0; }

#pragma unroll 4
    for (int c = 0; c < 32; c++) {
        float4 aq = *(const float4*)&As[c * 68 + ((rid ^ (c & 15)) << 2)];
        ulonglong2 bk0 = *(const ulonglong2*)&Bs[c * 68 + ((jid ^ (c & 15)) << 2)];
        ulonglong2 bk1 = *(const ulonglong2*)&Bs[(32 + c) * 68 + ((jid ^ (c & 15)) << 2)];
        float a4[4] = {aq.x, aq.y, aq.z, aq.w};
#pragma unroll
        for (int qi = 0; qi < 4; qi++) {
            ull a2 = pack2(a4[qi], a4[qi]);
            acc[qi][0][0] = fma2(a2, bk0.x, acc[qi][0][0]);
            acc[qi][0][1] = fma2(a2, bk0.y, acc[qi][0][1]);
            acc[qi][1][0] = fma2(a2, bk1.x, acc[qi][1][0]);
            acc[qi][1][1] = fma2(a2, bk1.y, acc[qi][1][1]);
        }
    }
#pragma unroll
    for (int qi = 0; qi < 4; qi++) {
        int row = rt * 64 + rid * 4 + qi;
#pragma unroll
        for (int g = 0; g < 2; g++) {
            int col = jt * 128 + g * 64 + jid * 4;
            float r0, r1, r2, r3;
            unpk(acc[qi][g][0], r0, r1);
            unpk(acc[qi][g][1], r2, r3);
            float* o = out + (size_t)row * 512 + col;
            asm volatile("red.global.add.v4.f32 [%0], {%1, %2, %3, %4};"
                         :: "l"(o), "f"(r0), "f"(r1), "f"(r2), "f"(r3)
                         : "memory");
        }
    }
}

extern "C" void kernel_launch(void* const* d_in, const int* in_sizes, int n_in,
                              void* d_out, int out_size) {
    const float* values = (const float*)d_in[0];
    const float* keys   = (const float*)d_in[1];
    const float* query  = (const float*)d_in[2];
    const float* pos    = (const float*)d_in[3];
    const float* rel    = (const float*)d_in[4];
    const float* mask   = (const float*)d_in[5];
    const float* Wv   = (const float*)d_in[6];
    const float* Wk   = (const float*)d_in[7];
    const float* Wq   = (const float*)d_in[8];
    const float* Wpq  = (const float*)d_in[9];
    const float* Wpk  = (const float*)d_in[10];
    const float* Wrk  = (const float*)d_in[11];
    const float* Wrq  = (const float*)d_in[12];
    const float* Wout = (const float*)d_in[13];
    const float* bout = (const float*)d_in[14];
    float* out = (float*)d_out;

    kA<<<dim3(8, 8, 4), 256>>>(query, keys, pos, values,
                               Wq, Wk, Wpq, Wpk, Wrk, Wrq, Wv,
                               mask, bout, out);
    kB<<<dim3(16, HH, 4), 256>>>();
    kC<<<dim3(LL / 2, NB), 256>>>(rel);
    kE<<<dim3(8, 4, 16), 256>>>(Wout, out);
}